// round 13
// baseline (speedup 1.0000x reference)
#include <cuda_runtime.h>
#include <cuda_bf16.h>
#include <math.h>
#include <cstdint>

#define NGENE 50000
#define NDIS  25000
#define FGENE 512
#define FDIS  256
#define CH    128
#define NE    150000

// ---------------- scratch ----------------
__device__ float  g_xs[(size_t)NGENE * 512];
__device__ float  g_geneA[(size_t)NGENE * CH];
__device__ float  g_disA[(size_t)NDIS * CH];
__device__ float  g_zb1[(size_t)NGENE * (CH + 4)];   // agg1 | denom1
__device__ float  g_zb2[(size_t)NGENE * (CH + 4)];   // agg2 | denom2
__device__ float  g_ls1[NGENE * 4];
__device__ float  g_ls2[NGENE * 4];
__device__ float  g_ld1[NGENE * 4];
__device__ float  g_ld2[NGENE * 4];
__device__ float  g_logits1[(NE + NDIS) * 4];
__device__ float  g_logits2[(NE + NGENE) * 4];
__device__ float  g_wld1[512], g_wld2[512], g_wls1[512], g_wls2[512];
__device__ float  g_wldpg[512], g_ldoffg[4];    // gene: scG*wld1, sum shG*wld1
__device__ float  g_wlspd[512], g_lsoffd[4];    // dis:  scD*wls1, sum shD*wls1
__device__ float  g_psG[400 * 128], g_pqG[400 * 128];
__device__ float  g_psD[400 * 128], g_pqD[400 * 128];
__device__ float  g_scaleG[CH], g_shiftG[CH], g_scaleD[CH], g_shiftD[CH];
__device__ __align__(256) __nv_bfloat16 g_btg_hi[512 * 128], g_btg_lo[512 * 128];
__device__ __align__(256) __nv_bfloat16 g_btd_hi[512 * 128], g_btd_lo[512 * 128];
__device__ __align__(256) __nv_bfloat16 g_bt1_hi[512 * 128], g_bt1_lo[512 * 128];
__device__ __align__(256) __nv_bfloat16 g_bt2_hi[512 * 128], g_bt2_lo[512 * 128];

// ---------------- small helpers ----------------
__device__ __forceinline__ float leaky(float x) { return x > 0.f ? x : 0.2f * x; }
__device__ __forceinline__ uint32_t smem_u32(const void* p) {
    uint32_t a;
    asm("{ .reg .u64 t; cvta.to.shared.u64 t, %1; cvt.u32.u64 %0, t; }" : "=r"(a) : "l"(p));
    return a;
}
__device__ __forceinline__ void mma16816(float* c, const uint32_t* a,
                                         uint32_t b0, uint32_t b1) {
    asm volatile("mma.sync.aligned.m16n8k16.row.col.f32.bf16.bf16.f32 "
                 "{%0,%1,%2,%3}, {%4,%5,%6,%7}, {%8,%9}, {%0,%1,%2,%3};"
                 : "+f"(c[0]), "+f"(c[1]), "+f"(c[2]), "+f"(c[3])
                 : "r"(a[0]), "r"(a[1]), "r"(a[2]), "r"(a[3]), "r"(b0), "r"(b1));
}
__device__ __forceinline__ void ldmx4(uint32_t* r, uint32_t addr) {
    asm volatile("ldmatrix.sync.aligned.m8n8.x4.shared.b16 {%0,%1,%2,%3}, [%4];"
                 : "=r"(r[0]), "=r"(r[1]), "=r"(r[2]), "=r"(r[3]) : "r"(addr));
}
__device__ __forceinline__ void cp16(uint32_t saddr, const void* g) {
    asm volatile("cp.async.cg.shared.global [%0], [%1], 16;" :: "r"(saddr), "l"(g));
}
__device__ __forceinline__ void cp_commit() {
    asm volatile("cp.async.commit_group;" ::: "memory");
}
template <int N_>
__device__ __forceinline__ void cp_wait() {
    asm volatile("cp.async.wait_group %0;" :: "n"(N_) : "memory");
}
__device__ __forceinline__ uint32_t pack_bf2(float x, float y) {
    __nv_bfloat162 t(__float2bfloat16(x), __float2bfloat16(y));
    return *(uint32_t*)&t;
}

// ---------------- batched prep: 4 splits + 4 folds ----------------
__device__ __forceinline__ void split_body(const float* B, __nv_bfloat16* thi,
                                           __nv_bfloat16* tlo, int K, int N,
                                           int idx, int total) {
    if (idx >= total) return;
    int k = idx / N, n = idx % N;
    float v = B[idx];
    __nv_bfloat16 h = __float2bfloat16(v);
    thi[(size_t)n * K + k] = h;
    tlo[(size_t)n * K + k] = __float2bfloat16(v - __bfloat162float(h));
}
// out[k*4+h] = <W[k, h*128 : h*128+128], a[h]>  (W is [128, 512], a is [4,128])
__device__ __forceinline__ void fold_body(const float* W, const float* a,
                                          float* out, int w, int lane) {
    int k = w >> 2, h = w & 3;
    float4 x = ((const float4*)(W + (size_t)k * 512 + h * 128))[lane];
    float4 y = ((const float4*)(a + h * 128))[lane];
    float s = x.x * y.x + x.y * y.y + x.z * y.z + x.w * y.w;
#pragma unroll
    for (int off = 16; off > 0; off >>= 1)
        s += __shfl_xor_sync(0xffffffffu, s, off);
    if (lane == 0) out[k * 4 + h] = s;
}

__global__ void prep_kernel(const float* __restrict__ Wg, const float* __restrict__ Wd,
                            const float* __restrict__ W1s, const float* __restrict__ W2s,
                            const float* __restrict__ W1d, const float* __restrict__ a1d,
                            const float* __restrict__ W2d, const float* __restrict__ a2d,
                            const float* __restrict__ a1s, const float* __restrict__ a2s) {
    const int b = blockIdx.x, tid = threadIdx.x;
    if (b < 256) {
        split_body(W1s, g_bt1_hi, g_bt1_lo, CH, 512, b * 256 + tid, CH * 512);
    } else if (b < 512) {
        split_body(W2s, g_bt2_hi, g_bt2_lo, CH, 512, (b - 256) * 256 + tid, CH * 512);
    } else if (b < 768) {
        split_body(Wg, g_btg_hi, g_btg_lo, FGENE, CH, (b - 512) * 256 + tid, FGENE * CH);
    } else if (b < 896) {
        split_body(Wd, g_btd_hi, g_btd_lo, FDIS, CH, (b - 768) * 256 + tid, FDIS * CH);
    } else if (b < 960) {
        fold_body(W1d, a1d, g_wld1, (b - 896) * 8 + (tid >> 5), tid & 31);
    } else if (b < 1024) {
        fold_body(W2d, a2d, g_wld2, (b - 960) * 8 + (tid >> 5), tid & 31);
    } else if (b < 1088) {
        fold_body(W1s, a1s, g_wls1, (b - 1024) * 8 + (tid >> 5), tid & 31);
    } else {
        fold_body(W2s, a2s, g_wls2, (b - 1088) * 8 + (tid >> 5), tid & 31);
    }
}

// ---------------- split-bf16 GEMM (templated on FLAGS) ----------------
// FLAGS: 1=bias, 2=relu, 8=colsum partials, 32=BN A-transform (bx==0 -> Aout)
#define SST 40

template <int FLAGS>
__global__ __launch_bounds__(256, 2)
void gemm_mma_kernel(const float* __restrict__ A,
                     const __nv_bfloat16* __restrict__ Bthi,
                     const __nv_bfloat16* __restrict__ Btlo,
                     const float* __restrict__ bias,
                     float* __restrict__ ps, float* __restrict__ pq,
                     const float* __restrict__ ascale, const float* __restrict__ ashift,
                     float* __restrict__ Aout,
                     float* __restrict__ C, int M, int N, int K)
{
    __shared__ __align__(16) __nv_bfloat16 smem[2][4][128 * SST];
    __shared__ float cs[128], cq[128];

    const int tid = threadIdx.x, wid = tid >> 5, lane = tid & 31;
    const int bm = blockIdx.y * 128, bn = blockIdx.x * 128;
    const int wm = (wid & 3) * 32, wn = (wid >> 2) * 64;
    const int lr = lane >> 2, lc = (lane & 3) * 2;
    const uint32_t sbase = smem_u32(&smem[0][0][0]);
    const uint32_t tilebytes = 128 * SST * 2;

    if ((FLAGS & 8) && tid < 128) { cs[tid] = 0.f; cq[tid] = 0.f; }

    float acc[2][8][4];
#pragma unroll
    for (int mt = 0; mt < 2; mt++)
#pragma unroll
        for (int nt = 0; nt < 8; nt++)
#pragma unroll
            for (int j = 0; j < 4; j++) acc[mt][nt][j] = 0.f;

    const int br_ = tid >> 2, bc8_ = (tid & 3) * 8;
    const int ar = tid >> 1, ac = (tid & 1) * 16;
    const bool arow_ok = (bm + ar < M);
    const int agr = arow_ok ? (bm + ar) : (M - 1);

    float av[16];

    auto ldgA = [&](int k0) {
        const float4* p = (const float4*)(A + (size_t)agr * K + k0 + ac);
        float4 v0 = p[0], v1 = p[1], v2 = p[2], v3 = p[3];
        av[0] = v0.x; av[1] = v0.y; av[2] = v0.z; av[3] = v0.w;
        av[4] = v1.x; av[5] = v1.y; av[6] = v1.z; av[7] = v1.w;
        av[8] = v2.x; av[9] = v2.y; av[10] = v2.z; av[11] = v2.w;
        av[12] = v3.x; av[13] = v3.y; av[14] = v3.z; av[15] = v3.w;
        if (FLAGS & 32) {
            const float4* sc = (const float4*)(ascale + k0 + ac);
            const float4* sh = (const float4*)(ashift + k0 + ac);
#pragma unroll
            for (int q = 0; q < 4; q++) {
                float4 s4 = sc[q], h4 = sh[q];
                av[4 * q + 0] = av[4 * q + 0] * s4.x + h4.x;
                av[4 * q + 1] = av[4 * q + 1] * s4.y + h4.y;
                av[4 * q + 2] = av[4 * q + 2] * s4.z + h4.z;
                av[4 * q + 3] = av[4 * q + 3] * s4.w + h4.w;
            }
            if (blockIdx.x == 0 && arow_ok) {
                float4* o = (float4*)(Aout + (size_t)(bm + ar) * K + k0 + ac);
                o[0] = make_float4(av[0], av[1], av[2], av[3]);
                o[1] = make_float4(av[4], av[5], av[6], av[7]);
                o[2] = make_float4(av[8], av[9], av[10], av[11]);
                o[3] = make_float4(av[12], av[13], av[14], av[15]);
            }
        }
    };
    auto stsA = [&](int buf) {
        uint32_t hi[8], lo[8];
#pragma unroll
        for (int j = 0; j < 8; j++) {
            float x0 = av[2 * j], x1 = av[2 * j + 1];
            __nv_bfloat16 h0 = __float2bfloat16(x0), h1 = __float2bfloat16(x1);
            hi[j] = pack_bf2(x0, x1);
            lo[j] = pack_bf2(x0 - __bfloat162float(h0), x1 - __bfloat162float(h1));
        }
        char* base = (char*)&smem[buf][0][0];
        const uint32_t off = (uint32_t)(ar * SST + ac) * 2;
        *(uint4*)(base + off)      = make_uint4(hi[0], hi[1], hi[2], hi[3]);
        *(uint4*)(base + off + 16) = make_uint4(hi[4], hi[5], hi[6], hi[7]);
        char* basel = (char*)&smem[buf][1][0];
        *(uint4*)(basel + off)      = make_uint4(lo[0], lo[1], lo[2], lo[3]);
        *(uint4*)(basel + off + 16) = make_uint4(lo[4], lo[5], lo[6], lo[7]);
    };
    auto issueB = [&](int buf, int k0) {
#pragma unroll
        for (int h = 0; h < 2; h++) {
            const int r = br_ + h * 64;
            const uint32_t soff = (uint32_t)(r * SST + bc8_) * 2;
            const uint32_t sb = sbase + buf * 4 * tilebytes + 2 * tilebytes + soff;
            const size_t boff = (size_t)(bn + r) * K + k0 + bc8_;
            cp16(sb, Bthi + boff);
            cp16(sb + tilebytes, Btlo + boff);
        }
        cp_commit();
    };

    const int nch = K >> 5;
    ldgA(0); issueB(0, 0); stsA(0);

    int buf = 0;
    for (int t = 0; t < nch; t++) {
        const bool has = (t + 1 < nch);
        if (has) {
            ldgA((t + 1) << 5);
            issueB(buf ^ 1, (t + 1) << 5);
            cp_wait<1>();
        } else {
            cp_wait<0>();
        }
        __syncthreads();

        const uint32_t sb = sbase + buf * 4 * tilebytes;
        const uint32_t sAh = sb, sAl = sb + tilebytes;
        const uint32_t sBh = sb + 2 * tilebytes, sBl = sb + 3 * tilebytes;

        const int arow = wm + (lane & 15);
        const int acol_off = (lane & 16) ? 8 : 0;
        const int brow = wn + (lane & 7) + ((lane & 16) ? 8 : 0);
        const int bcol_off = (lane & 8) ? 8 : 0;

#pragma unroll
        for (int ks = 0; ks < 2; ks++) {
            const int kb = ks * 16;
            uint32_t ah[2][4], al[2][4];
#pragma unroll
            for (int mt = 0; mt < 2; mt++) {
                const uint32_t aaddr = (uint32_t)(((arow + mt * 16) * SST) + kb + acol_off) * 2;
                ldmx4(ah[mt], sAh + aaddr);
                ldmx4(al[mt], sAl + aaddr);
            }
#pragma unroll
            for (int p = 0; p < 4; p++) {
                uint32_t bh[4], bl[4];
                const uint32_t baddr = (uint32_t)(((brow + p * 16) * SST) + kb + bcol_off) * 2;
                ldmx4(bh, sBh + baddr);
                ldmx4(bl, sBl + baddr);
#pragma unroll
                for (int sub = 0; sub < 2; sub++) {
                    const int nt = p * 2 + sub;
                    const uint32_t bh0 = bh[sub * 2], bh1 = bh[sub * 2 + 1];
                    const uint32_t bl0 = bl[sub * 2], bl1 = bl[sub * 2 + 1];
#pragma unroll
                    for (int mt = 0; mt < 2; mt++) {
                        mma16816(acc[mt][nt], ah[mt], bh0, bh1);
                        mma16816(acc[mt][nt], ah[mt], bl0, bl1);
                        mma16816(acc[mt][nt], al[mt], bh0, bh1);
                    }
                }
            }
        }
        __syncthreads();
        if (has) stsA(buf ^ 1);
        buf ^= 1;
    }

    // ---------------- epilogue ----------------
#pragma unroll
    for (int mt = 0; mt < 2; mt++) {
        const int r0 = bm + wm + mt * 16 + lr;
        const bool ok0 = r0 < M, ok1 = (r0 + 8) < M;
#pragma unroll
        for (int nt = 0; nt < 8; nt++) {
            const int col = bn + wn + nt * 8 + lc;
            float2 v0 = make_float2(acc[mt][nt][0], acc[mt][nt][1]);
            float2 v1 = make_float2(acc[mt][nt][2], acc[mt][nt][3]);
            if (FLAGS & 1) {
                float2 bb = *(const float2*)(bias + col);
                v0.x += bb.x; v0.y += bb.y; v1.x += bb.x; v1.y += bb.y;
            }
            if (FLAGS & 2) {
                v0.x = fmaxf(v0.x, 0.f); v0.y = fmaxf(v0.y, 0.f);
                v1.x = fmaxf(v1.x, 0.f); v1.y = fmaxf(v1.y, 0.f);
            }
            if (ok0) *(float2*)(C + (size_t)r0 * N + col) = v0;
            if (ok1) *(float2*)(C + (size_t)(r0 + 8) * N + col) = v1;
            if (FLAGS & 8) {
                float s0 = (ok0 ? v0.x : 0.f) + (ok1 ? v1.x : 0.f);
                float s1 = (ok0 ? v0.y : 0.f) + (ok1 ? v1.y : 0.f);
                float q0 = (ok0 ? v0.x * v0.x : 0.f) + (ok1 ? v1.x * v1.x : 0.f);
                float q1 = (ok0 ? v0.y * v0.y : 0.f) + (ok1 ? v1.y * v1.y : 0.f);
                const int cc = wn + nt * 8 + lc;
                atomicAdd(&cs[cc], s0); atomicAdd(&cs[cc + 1], s1);
                atomicAdd(&cq[cc], q0); atomicAdd(&cq[cc + 1], q1);
            }
        }
    }
    if (FLAGS & 8) {
        __syncthreads();
        if (tid < 128) {
            ps[blockIdx.y * 128 + tid] = cs[tid];
            pq[blockIdx.y * 128 + tid] = cq[tid];
        }
    }
}

// ---------------- BatchNorm params (+ optional fold: wldp = scale*wld, off = sum shift*wld) --
__global__ void bn_params_kernel(const float* __restrict__ gamma,
                                 const float* __restrict__ beta,
                                 const float* __restrict__ ps,
                                 const float* __restrict__ pq,
                                 int nb, int M,
                                 float* __restrict__ scale, float* __restrict__ shift,
                                 const float* __restrict__ wld_in,
                                 float* __restrict__ wldp, float* __restrict__ ldoff) {
    __shared__ double ss[4][128], sq[4][128];
    __shared__ float fsc[128], fsh[128], soff[4];
    int c = threadIdx.x & 127, part = threadIdx.x >> 7;
    double s = 0.0, q = 0.0;
    for (int b = part; b < nb; b += 4) { s += ps[b * 128 + c]; q += pq[b * 128 + c]; }
    ss[part][c] = s; sq[part][c] = q;
    if (threadIdx.x < 4) soff[threadIdx.x] = 0.f;
    __syncthreads();
    if (threadIdx.x < 128) {
        double S = ss[0][c] + ss[1][c] + ss[2][c] + ss[3][c];
        double Q = sq[0][c] + sq[1][c] + sq[2][c] + sq[3][c];
        double mu = S / M;
        double var = Q / M - mu * mu;
        float sc = gamma[c] * rsqrtf((float)var + 1e-5f);
        float sh = beta[c] - (float)mu * sc;
        scale[c] = sc; shift[c] = sh;
        fsc[c] = sc; fsh[c] = sh;
    }
    if (wld_in) {
        __syncthreads();
        int h = threadIdx.x >> 7;
        float w = wld_in[c * 4 + h];
        wldp[c * 4 + h] = fsc[c] * w;
        float p = fsh[c] * w;
#pragma unroll
        for (int off = 16; off > 0; off >>= 1)
            p += __shfl_xor_sync(0xffffffffu, p, off);
        if ((threadIdx.x & 31) == 0) atomicAdd(&soff[h], p);
        __syncthreads();
        if (threadIdx.x < 4) ldoff[threadIdx.x] = soff[threadIdx.x];
    }
}

// row dot: out[i][h] = sum_c A[i][c]*wldp[c][h] + ldoff[h]  (warp per row)
__global__ void ld_raw_kernel(const float* __restrict__ A, int M,
                              const float* __restrict__ wldp,
                              const float* __restrict__ ldoff,
                              float* __restrict__ ld_out) {
    int i = blockIdx.x * blockDim.x + threadIdx.x;
    if (i >= M * (CH / 4)) return;
    int c = (i & 31) * 4;
    float4 v = ((const float4*)A)[i];
    float4 w0 = ((const float4*)wldp)[c + 0];
    float4 w1 = ((const float4*)wldp)[c + 1];
    float4 w2 = ((const float4*)wldp)[c + 2];
    float4 w3 = ((const float4*)wldp)[c + 3];
    float p0 = v.x * w0.x + v.y * w1.x + v.z * w2.x + v.w * w3.x;
    float p1 = v.x * w0.y + v.y * w1.y + v.z * w2.y + v.w * w3.y;
    float p2 = v.x * w0.z + v.y * w1.z + v.z * w2.z + v.w * w3.z;
    float p3 = v.x * w0.w + v.y * w1.w + v.z * w2.w + v.w * w3.w;
#pragma unroll
    for (int off = 16; off > 0; off >>= 1) {
        p0 += __shfl_xor_sync(0xffffffffu, p0, off);
        p1 += __shfl_xor_sync(0xffffffffu, p1, off);
        p2 += __shfl_xor_sync(0xffffffffu, p2, off);
        p3 += __shfl_xor_sync(0xffffffffu, p3, off);
    }
    if ((i & 31) == 0)
        ((float4*)ld_out)[i >> 5] = make_float4(p0 + ldoff[0], p1 + ldoff[1],
                                                p2 + ldoff[2], p3 + ldoff[3]);
}

// ---------------- GAT pieces ----------------
__global__ void gat_edge_kernel(const int* __restrict__ src, const int* __restrict__ dst,
                                const float* __restrict__ ls, const float* __restrict__ ld,
                                float* __restrict__ denom, float* __restrict__ logits,
                                int E, int n_loop) {
    int e = blockIdx.x * blockDim.x + threadIdx.x;
    if (e >= E + n_loop) return;
    int s, d; bool mask;
    if (e < E) { s = src[e]; d = dst[e]; mask = (s != d); }
    else       { s = d = e - E; mask = true; }
    float4 a = ((const float4*)ls)[s];
    float4 b = ((const float4*)ld)[d];
    float p0 = mask ? expf(leaky(a.x + b.x)) : 0.f;
    float p1 = mask ? expf(leaky(a.y + b.y)) : 0.f;
    float p2 = mask ? expf(leaky(a.z + b.z)) : 0.f;
    float p3 = mask ? expf(leaky(a.w + b.w)) : 0.f;
    ((float4*)logits)[e] = make_float4(p0, p1, p2, p3);
    asm volatile("red.global.add.v4.f32 [%0], {%1, %2, %3, %4};"
                 :: "l"(denom + d * 4), "f"(p0), "f"(p1), "f"(p2), "f"(p3) : "memory");
}

__global__ void gat_pass3_kernel(const int* __restrict__ src, const int* __restrict__ dst,
                                 const float* __restrict__ logits,
                                 const float* __restrict__ denom,
                                 float* __restrict__ agg, int E, int n_loop) {
    int w = (blockIdx.x * blockDim.x + threadIdx.x) >> 5;
    int lane = threadIdx.x & 31;
    if (w >= E + n_loop) return;
    int s, d;
    if (w < E) { s = src[w]; d = dst[w]; }
    else       { s = d = w - E; }
    float4 P = ((const float4*)logits)[w];
    float4 D = ((const float4*)denom)[d];
    float a0 = 0.25f * P.x / (D.x > 0.f ? D.x : 1.f);
    float a1 = 0.25f * P.y / (D.y > 0.f ? D.y : 1.f);
    float a2 = 0.25f * P.z / (D.z > 0.f ? D.z : 1.f);
    float a3 = 0.25f * P.w / (D.w > 0.f ? D.w : 1.f);
    const float4* xr = (const float4*)g_xs + (size_t)s * 128;
    float4 x0 = xr[lane], x1 = xr[32 + lane], x2 = xr[64 + lane], x3 = xr[96 + lane];
    float r0 = a0 * x0.x + a1 * x1.x + a2 * x2.x + a3 * x3.x;
    float r1 = a0 * x0.y + a1 * x1.y + a2 * x2.y + a3 * x3.y;
    float r2 = a0 * x0.z + a1 * x1.z + a2 * x2.z + a3 * x3.z;
    float r3 = a0 * x0.w + a1 * x1.w + a2 * x2.w + a3 * x3.w;
    float* out = agg + (size_t)d * CH + lane * 4;
    asm volatile("red.global.add.v4.f32 [%0], {%1, %2, %3, %4};"
                 :: "l"(out), "f"(r0), "f"(r1), "f"(r2), "f"(r3) : "memory");
}

// combine: gout = [BN(gin) if scale] + agg + bias; optional dual folds (ld2, ls2)
__global__ void combine_kernel(const float* __restrict__ gin, float* __restrict__ gout,
                               const float* __restrict__ bias,
                               const float* __restrict__ agg,
                               const float* __restrict__ scale,
                               const float* __restrict__ shift,
                               const float* __restrict__ wld, float* __restrict__ ld_out,
                               const float* __restrict__ wls, float* __restrict__ ls_out) {
    int i = blockIdx.x * blockDim.x + threadIdx.x;
    if (i >= NGENE * 32) return;
    int c = (i & 31) * 4;
    float4 v = ((const float4*)gin)[i];
    if (scale) {
        v.x = v.x * scale[c + 0] + shift[c + 0];
        v.y = v.y * scale[c + 1] + shift[c + 1];
        v.z = v.z * scale[c + 2] + shift[c + 2];
        v.w = v.w * scale[c + 3] + shift[c + 3];
    }
    float4 ag = ((const float4*)agg)[i];
    v.x += ag.x + bias[c + 0];
    v.y += ag.y + bias[c + 1];
    v.z += ag.z + bias[c + 2];
    v.w += ag.w + bias[c + 3];
    ((float4*)gout)[i] = v;
    if (wld) {
        float4 w0 = ((const float4*)wld)[c + 0];
        float4 w1 = ((const float4*)wld)[c + 1];
        float4 w2 = ((const float4*)wld)[c + 2];
        float4 w3 = ((const float4*)wld)[c + 3];
        float p0 = v.x * w0.x + v.y * w1.x + v.z * w2.x + v.w * w3.x;
        float p1 = v.x * w0.y + v.y * w1.y + v.z * w2.y + v.w * w3.y;
        float p2 = v.x * w0.z + v.y * w1.z + v.z * w2.z + v.w * w3.z;
        float p3 = v.x * w0.w + v.y * w1.w + v.z * w2.w + v.w * w3.w;
        float4 u0 = ((const float4*)wls)[c + 0];
        float4 u1 = ((const float4*)wls)[c + 1];
        float4 u2 = ((const float4*)wls)[c + 2];
        float4 u3 = ((const float4*)wls)[c + 3];
        float q0 = v.x * u0.x + v.y * u1.x + v.z * u2.x + v.w * u3.x;
        float q1 = v.x * u0.y + v.y * u1.y + v.z * u2.y + v.w * u3.y;
        float q2 = v.x * u0.z + v.y * u1.z + v.z * u2.z + v.w * u3.z;
        float q3 = v.x * u0.w + v.y * u1.w + v.z * u2.w + v.w * u3.w;
#pragma unroll
        for (int off = 16; off > 0; off >>= 1) {
            p0 += __shfl_xor_sync(0xffffffffu, p0, off);
            p1 += __shfl_xor_sync(0xffffffffu, p1, off);
            p2 += __shfl_xor_sync(0xffffffffu, p2, off);
            p3 += __shfl_xor_sync(0xffffffffu, p3, off);
            q0 += __shfl_xor_sync(0xffffffffu, q0, off);
            q1 += __shfl_xor_sync(0xffffffffu, q1, off);
            q2 += __shfl_xor_sync(0xffffffffu, q2, off);
            q3 += __shfl_xor_sync(0xffffffffu, q3, off);
        }
        if ((i & 31) == 0) {
            ((float4*)ld_out)[i >> 5] = make_float4(p0, p1, p2, p3);
            ((float4*)ls_out)[i >> 5] = make_float4(q0, q1, q2, q3);
        }
    }
}

// ---------------- launch ----------------
#define SYM(p, s) cudaGetSymbolAddress((void**)&p, s)

extern "C" void kernel_launch(void* const* d_in, const int* in_sizes, int n_in,
                              void* d_out, int out_size) {
    const float* x_gene = (const float*)d_in[0];
    const float* x_dis  = (const float*)d_in[1];
    const int* e1_src = (const int*)d_in[2];
    const int* e1_dst = (const int*)d_in[3];
    const int* e2_src = (const int*)d_in[4];
    const int* e2_dst = (const int*)d_in[5];
    const float* Wg = (const float*)d_in[6];
    const float* bg = (const float*)d_in[7];
    const float* gg = (const float*)d_in[8];
    const float* betag = (const float*)d_in[9];
    const float* Wd = (const float*)d_in[10];
    const float* bd = (const float*)d_in[11];
    const float* gd = (const float*)d_in[12];
    const float* betad = (const float*)d_in[13];
    const float* W1s = (const float*)d_in[14];
    const float* W1d = (const float*)d_in[15];
    const float* a1s = (const float*)d_in[16];
    const float* a1d = (const float*)d_in[17];
    const float* b1  = (const float*)d_in[18];
    const float* W2s = (const float*)d_in[19];
    const float* W2d = (const float*)d_in[20];
    const float* a2s = (const float*)d_in[21];
    const float* a2d = (const float*)d_in[22];
    const float* b2  = (const float*)d_in[23];

    float* out_gene = (float*)d_out;
    float* out_dis  = (float*)d_out + (size_t)NGENE * CH;

    float *xs, *geneA, *disA, *zb1, *zb2, *ls1, *ls2, *ld1, *ld2, *lg1, *lg2;
    float *wld1, *wld2, *wls1, *wls2, *wldpg, *ldoffg, *wlspd, *lsoffd;
    float *psG, *pqG, *psD, *pqD, *scG, *shG, *scD, *shD;
    __nv_bfloat16 *bt1_h, *bt1_l, *bt2_h, *bt2_l, *btg_h, *btg_l, *btd_h, *btd_l;
    SYM(xs, g_xs); SYM(geneA, g_geneA); SYM(disA, g_disA);
    SYM(zb1, g_zb1); SYM(zb2, g_zb2);
    SYM(ls1, g_ls1); SYM(ls2, g_ls2); SYM(ld1, g_ld1); SYM(ld2, g_ld2);
    SYM(lg1, g_logits1); SYM(lg2, g_logits2);
    SYM(wld1, g_wld1); SYM(wld2, g_wld2); SYM(wls1, g_wls1); SYM(wls2, g_wls2);
    SYM(wldpg, g_wldpg); SYM(ldoffg, g_ldoffg); SYM(wlspd, g_wlspd); SYM(lsoffd, g_lsoffd);
    SYM(psG, g_psG); SYM(pqG, g_pqG); SYM(psD, g_psD); SYM(pqD, g_pqD);
    SYM(scG, g_scaleG); SYM(shG, g_shiftG); SYM(scD, g_scaleD); SYM(shD, g_shiftD);
    SYM(btg_h, g_btg_hi); SYM(btg_l, g_btg_lo); SYM(btd_h, g_btd_hi); SYM(btd_l, g_btd_lo);
    SYM(bt1_h, g_bt1_hi); SYM(bt1_l, g_bt1_lo); SYM(bt2_h, g_bt2_hi); SYM(bt2_l, g_bt2_lo);

    float* agg1 = zb1;  float* dn1 = zb1 + (size_t)NGENE * CH;
    float* agg2 = zb2;  float* dn2 = zb2 + (size_t)NGENE * CH;

    cudaStream_t s1, s2;
    cudaStreamCreateWithFlags(&s1, cudaStreamNonBlocking);
    cudaStreamCreateWithFlags(&s2, cudaStreamNonBlocking);
    cudaEvent_t e0, e_prep, e_ls1, e_xs1, e_z1, e_z2, e_c1, e_e2;
    cudaEventCreateWithFlags(&e0, cudaEventDisableTiming);
    cudaEventCreateWithFlags(&e_prep, cudaEventDisableTiming);
    cudaEventCreateWithFlags(&e_ls1, cudaEventDisableTiming);
    cudaEventCreateWithFlags(&e_xs1, cudaEventDisableTiming);
    cudaEventCreateWithFlags(&e_z1, cudaEventDisableTiming);
    cudaEventCreateWithFlags(&e_z2, cudaEventDisableTiming);
    cudaEventCreateWithFlags(&e_c1, cudaEventDisableTiming);
    cudaEventCreateWithFlags(&e_e2, cudaEventDisableTiming);

    cudaEventRecord(e0, 0);
    cudaStreamWaitEvent(s1, e0, 0);
    cudaStreamWaitEvent(s2, e0, 0);

    const int GY_G = (NGENE + 127) / 128;   // 391
    const int GY_D = (NDIS + 127) / 128;    // 196

    // ---- s2: single prep kernel + zeroing ----
    prep_kernel<<<1152, 256, 0, s2>>>(Wg, Wd, W1s, W2s, W1d, a1d, W2d, a2d, a1s, a2s);
    cudaEventRecord(e_prep, s2);
    cudaMemsetAsync(zb1, 0, (size_t)NGENE * (CH + 4) * sizeof(float), s2);
    cudaEventRecord(e_z1, s2);
    cudaMemsetAsync(zb2, 0, (size_t)NGENE * (CH + 4) * sizeof(float), s2);
    cudaEventRecord(e_z2, s2);

    // ---- s1: dis encode -> ls1 (cheap) -> xs1 GEMM ----
    cudaStreamWaitEvent(s1, e_prep, 0);
    gemm_mma_kernel<1 | 2 | 8><<<dim3(1, GY_D), 256, 0, s1>>>(
        x_dis, btd_h, btd_l, bd, psD, pqD, nullptr, nullptr, nullptr,
        disA, NDIS, CH, FDIS);
    bn_params_kernel<<<1, 512, 0, s1>>>(gd, betad, psD, pqD, GY_D, NDIS, scD, shD,
                                        wls1, wlspd, lsoffd);
    ld_raw_kernel<<<(NDIS * 32 + 255) / 256, 256, 0, s1>>>(disA, NDIS, wlspd, lsoffd, ls1);
    cudaEventRecord(e_ls1, s1);
    gemm_mma_kernel<32><<<dim3(4, GY_D), 256, 0, s1>>>(
        disA, bt1_h, bt1_l, nullptr, nullptr, nullptr, scD, shD, out_dis,
        xs, NDIS, 512, CH);
    cudaEventRecord(e_xs1, s1);

    // ---- s0: gene encode -> ld1 ----
    cudaStreamWaitEvent(0, e_prep, 0);
    gemm_mma_kernel<1 | 2 | 8><<<dim3(1, GY_G), 256>>>(
        x_gene, btg_h, btg_l, bg, psG, pqG, nullptr, nullptr, nullptr,
        geneA, NGENE, CH, FGENE);
    bn_params_kernel<<<1, 512>>>(gg, betag, psG, pqG, GY_G, NGENE, scG, shG,
                                 wld1, wldpg, ldoffg);
    ld_raw_kernel<<<(NGENE * 32 + 255) / 256, 256>>>(geneA, NGENE, wldpg, ldoffg, ld1);

    // ---- relation 1 on s0 (edge1 overlaps xs1 GEMM tail) ----
    cudaStreamWaitEvent(0, e_ls1, 0);
    cudaStreamWaitEvent(0, e_z1, 0);
    {
        const int E = NE, n_loop = NDIS, ET = E + n_loop;
        gat_edge_kernel<<<(ET + 255) / 256, 256>>>(e1_src, e1_dst, ls1, ld1, dn1, lg1, E, n_loop);
        cudaStreamWaitEvent(0, e_xs1, 0);
        gat_pass3_kernel<<<(ET + 7) / 8, 256>>>(e1_src, e1_dst, lg1, dn1, agg1, E, n_loop);
    }
    // combine1: BN(geneA)+agg1+b1 -> geneA, dual fold -> ld2, ls2
    combine_kernel<<<(NGENE * 32 + 255) / 256, 256>>>(geneA, geneA, b1, agg1,
                                                      scG, shG, wld2, ld2, wls2, ls2);
    cudaEventRecord(e_c1, 0);

    // ---- relation 2: xs2 GEMM on s0, edge2 concurrently on s1 ----
    gemm_mma_kernel<0><<<dim3(4, GY_G), 256>>>(
        geneA, bt2_h, bt2_l, nullptr, nullptr, nullptr, nullptr, nullptr, nullptr,
        xs, NGENE, 512, CH);
    cudaStreamWaitEvent(s1, e_c1, 0);
    cudaStreamWaitEvent(s1, e_z2, 0);
    {
        const int E = NE, n_loop = NGENE, ET = E + n_loop;
        gat_edge_kernel<<<(ET + 255) / 256, 256, 0, s1>>>(e2_src, e2_dst, ls2, ld2, dn2, lg2,
                                                          E, n_loop);
        cudaEventRecord(e_e2, s1);
        cudaStreamWaitEvent(0, e_e2, 0);
        gat_pass3_kernel<<<(ET + 7) / 8, 256>>>(e2_src, e2_dst, lg2, dn2, agg2, E, n_loop);
    }
    combine_kernel<<<(NGENE * 32 + 255) / 256, 256>>>(geneA, out_gene, b2, agg2,
                                                      nullptr, nullptr, nullptr, nullptr,
                                                      nullptr, nullptr);

    cudaEventDestroy(e0);
    cudaEventDestroy(e_prep);
    cudaEventDestroy(e_ls1);
    cudaEventDestroy(e_xs1);
    cudaEventDestroy(e_z1);
    cudaEventDestroy(e_z2);
    cudaEventDestroy(e_c1);
    cudaEventDestroy(e_e2);
    cudaStreamDestroy(s1);
    cudaStreamDestroy(s2);
}

// round 14
// speedup vs baseline: 1.0630x; 1.0630x over previous
#include <cuda_runtime.h>
#include <cuda_bf16.h>
#include <cuda_fp16.h>
#include <math.h>
#include <cstdint>

#define NGENE 50000
#define NDIS  25000
#define FGENE 512
#define FDIS  256
#define CH    128
#define NE    150000

// ---------------- scratch ----------------
__device__ __half g_xs[(size_t)NGENE * 512];         // fp16 value tensor
__device__ float  g_geneA[(size_t)NGENE * CH];
__device__ float  g_disA[(size_t)NDIS * CH];
__device__ float  g_zb1[(size_t)NGENE * (CH + 4)];   // agg1 | denom1
__device__ float  g_zb2[(size_t)NGENE * (CH + 4)];   // agg2 | denom2
__device__ float  g_ls1[NGENE * 4];
__device__ float  g_ls2[NGENE * 4];
__device__ float  g_ld1[NGENE * 4];
__device__ float  g_ld2[NGENE * 4];
__device__ float  g_logits1[(NE + NDIS) * 4];
__device__ float  g_logits2[(NE + NGENE) * 4];
__device__ float  g_wld1[512], g_wld2[512], g_wls1[512], g_wls2[512];
__device__ float  g_wldpg[512], g_ldoffg[4];
__device__ float  g_wlspd[512], g_lsoffd[4];
__device__ float  g_psG[400 * 128], g_pqG[400 * 128];
__device__ float  g_psD[400 * 128], g_pqD[400 * 128];
__device__ float  g_scaleG[CH], g_shiftG[CH], g_scaleD[CH], g_shiftD[CH];
__device__ __align__(256) __nv_bfloat16 g_btg_hi[512 * 128], g_btg_lo[512 * 128];
__device__ __align__(256) __nv_bfloat16 g_btd_hi[512 * 128], g_btd_lo[512 * 128];
__device__ __align__(256) __nv_bfloat16 g_bt1_hi[512 * 128], g_bt1_lo[512 * 128];
__device__ __align__(256) __nv_bfloat16 g_bt2_hi[512 * 128], g_bt2_lo[512 * 128];

// ---------------- small helpers ----------------
__device__ __forceinline__ float leaky(float x) { return x > 0.f ? x : 0.2f * x; }
__device__ __forceinline__ uint32_t smem_u32(const void* p) {
    uint32_t a;
    asm("{ .reg .u64 t; cvta.to.shared.u64 t, %1; cvt.u32.u64 %0, t; }" : "=r"(a) : "l"(p));
    return a;
}
__device__ __forceinline__ void mma16816(float* c, const uint32_t* a,
                                         uint32_t b0, uint32_t b1) {
    asm volatile("mma.sync.aligned.m16n8k16.row.col.f32.bf16.bf16.f32 "
                 "{%0,%1,%2,%3}, {%4,%5,%6,%7}, {%8,%9}, {%0,%1,%2,%3};"
                 : "+f"(c[0]), "+f"(c[1]), "+f"(c[2]), "+f"(c[3])
                 : "r"(a[0]), "r"(a[1]), "r"(a[2]), "r"(a[3]), "r"(b0), "r"(b1));
}
__device__ __forceinline__ void ldmx4(uint32_t* r, uint32_t addr) {
    asm volatile("ldmatrix.sync.aligned.m8n8.x4.shared.b16 {%0,%1,%2,%3}, [%4];"
                 : "=r"(r[0]), "=r"(r[1]), "=r"(r[2]), "=r"(r[3]) : "r"(addr));
}
__device__ __forceinline__ void cp16(uint32_t saddr, const void* g) {
    asm volatile("cp.async.cg.shared.global [%0], [%1], 16;" :: "r"(saddr), "l"(g));
}
__device__ __forceinline__ void cp_commit() {
    asm volatile("cp.async.commit_group;" ::: "memory");
}
template <int N_>
__device__ __forceinline__ void cp_wait() {
    asm volatile("cp.async.wait_group %0;" :: "n"(N_) : "memory");
}
__device__ __forceinline__ uint32_t pack_bf2(float x, float y) {
    __nv_bfloat162 t(__float2bfloat16(x), __float2bfloat16(y));
    return *(uint32_t*)&t;
}

// ---------------- batched prep: 4 splits + 4 folds ----------------
__device__ __forceinline__ void split_body(const float* B, __nv_bfloat16* thi,
                                           __nv_bfloat16* tlo, int K, int N,
                                           int idx, int total) {
    if (idx >= total) return;
    int k = idx / N, n = idx % N;
    float v = B[idx];
    __nv_bfloat16 h = __float2bfloat16(v);
    thi[(size_t)n * K + k] = h;
    tlo[(size_t)n * K + k] = __float2bfloat16(v - __bfloat162float(h));
}
__device__ __forceinline__ void fold_body(const float* W, const float* a,
                                          float* out, int w, int lane) {
    int k = w >> 2, h = w & 3;
    float4 x = ((const float4*)(W + (size_t)k * 512 + h * 128))[lane];
    float4 y = ((const float4*)(a + h * 128))[lane];
    float s = x.x * y.x + x.y * y.y + x.z * y.z + x.w * y.w;
#pragma unroll
    for (int off = 16; off > 0; off >>= 1)
        s += __shfl_xor_sync(0xffffffffu, s, off);
    if (lane == 0) out[k * 4 + h] = s;
}

__global__ void prep_kernel(const float* __restrict__ Wg, const float* __restrict__ Wd,
                            const float* __restrict__ W1s, const float* __restrict__ W2s,
                            const float* __restrict__ W1d, const float* __restrict__ a1d,
                            const float* __restrict__ W2d, const float* __restrict__ a2d,
                            const float* __restrict__ a1s, const float* __restrict__ a2s) {
    const int b = blockIdx.x, tid = threadIdx.x;
    if (b < 256) {
        split_body(W1s, g_bt1_hi, g_bt1_lo, CH, 512, b * 256 + tid, CH * 512);
    } else if (b < 512) {
        split_body(W2s, g_bt2_hi, g_bt2_lo, CH, 512, (b - 256) * 256 + tid, CH * 512);
    } else if (b < 768) {
        split_body(Wg, g_btg_hi, g_btg_lo, FGENE, CH, (b - 512) * 256 + tid, FGENE * CH);
    } else if (b < 896) {
        split_body(Wd, g_btd_hi, g_btd_lo, FDIS, CH, (b - 768) * 256 + tid, FDIS * CH);
    } else if (b < 960) {
        fold_body(W1d, a1d, g_wld1, (b - 896) * 8 + (tid >> 5), tid & 31);
    } else if (b < 1024) {
        fold_body(W2d, a2d, g_wld2, (b - 960) * 8 + (tid >> 5), tid & 31);
    } else if (b < 1088) {
        fold_body(W1s, a1s, g_wls1, (b - 1024) * 8 + (tid >> 5), tid & 31);
    } else {
        fold_body(W2s, a2s, g_wls2, (b - 1088) * 8 + (tid >> 5), tid & 31);
    }
}

// ---------------- split-bf16 GEMM (templated on FLAGS) ----------------
// FLAGS: 1=bias, 2=relu, 8=colsum partials, 32=BN A-transform (bx==0 -> Aout),
//        64=store C as fp16
#define SST 40

template <int FLAGS>
__global__ __launch_bounds__(256, 2)
void gemm_mma_kernel(const float* __restrict__ A,
                     const __nv_bfloat16* __restrict__ Bthi,
                     const __nv_bfloat16* __restrict__ Btlo,
                     const float* __restrict__ bias,
                     float* __restrict__ ps, float* __restrict__ pq,
                     const float* __restrict__ ascale, const float* __restrict__ ashift,
                     float* __restrict__ Aout,
                     void* __restrict__ Cv, int M, int N, int K)
{
    __shared__ __align__(16) __nv_bfloat16 smem[2][4][128 * SST];
    __shared__ float cs[128], cq[128];

    const int tid = threadIdx.x, wid = tid >> 5, lane = tid & 31;
    const int bm = blockIdx.y * 128, bn = blockIdx.x * 128;
    const int wm = (wid & 3) * 32, wn = (wid >> 2) * 64;
    const int lr = lane >> 2, lc = (lane & 3) * 2;
    const uint32_t sbase = smem_u32(&smem[0][0][0]);
    const uint32_t tilebytes = 128 * SST * 2;

    if ((FLAGS & 8) && tid < 128) { cs[tid] = 0.f; cq[tid] = 0.f; }

    float acc[2][8][4];
#pragma unroll
    for (int mt = 0; mt < 2; mt++)
#pragma unroll
        for (int nt = 0; nt < 8; nt++)
#pragma unroll
            for (int j = 0; j < 4; j++) acc[mt][nt][j] = 0.f;

    const int br_ = tid >> 2, bc8_ = (tid & 3) * 8;
    const int ar = tid >> 1, ac = (tid & 1) * 16;
    const bool arow_ok = (bm + ar < M);
    const int agr = arow_ok ? (bm + ar) : (M - 1);

    float av[16];

    auto ldgA = [&](int k0) {
        const float4* p = (const float4*)(A + (size_t)agr * K + k0 + ac);
        float4 v0 = p[0], v1 = p[1], v2 = p[2], v3 = p[3];
        av[0] = v0.x; av[1] = v0.y; av[2] = v0.z; av[3] = v0.w;
        av[4] = v1.x; av[5] = v1.y; av[6] = v1.z; av[7] = v1.w;
        av[8] = v2.x; av[9] = v2.y; av[10] = v2.z; av[11] = v2.w;
        av[12] = v3.x; av[13] = v3.y; av[14] = v3.z; av[15] = v3.w;
        if (FLAGS & 32) {
            const float4* sc = (const float4*)(ascale + k0 + ac);
            const float4* sh = (const float4*)(ashift + k0 + ac);
#pragma unroll
            for (int q = 0; q < 4; q++) {
                float4 s4 = sc[q], h4 = sh[q];
                av[4 * q + 0] = av[4 * q + 0] * s4.x + h4.x;
                av[4 * q + 1] = av[4 * q + 1] * s4.y + h4.y;
                av[4 * q + 2] = av[4 * q + 2] * s4.z + h4.z;
                av[4 * q + 3] = av[4 * q + 3] * s4.w + h4.w;
            }
            if (blockIdx.x == 0 && arow_ok) {
                float4* o = (float4*)(Aout + (size_t)(bm + ar) * K + k0 + ac);
                o[0] = make_float4(av[0], av[1], av[2], av[3]);
                o[1] = make_float4(av[4], av[5], av[6], av[7]);
                o[2] = make_float4(av[8], av[9], av[10], av[11]);
                o[3] = make_float4(av[12], av[13], av[14], av[15]);
            }
        }
    };
    auto stsA = [&](int buf) {
        uint32_t hi[8], lo[8];
#pragma unroll
        for (int j = 0; j < 8; j++) {
            float x0 = av[2 * j], x1 = av[2 * j + 1];
            __nv_bfloat16 h0 = __float2bfloat16(x0), h1 = __float2bfloat16(x1);
            hi[j] = pack_bf2(x0, x1);
            lo[j] = pack_bf2(x0 - __bfloat162float(h0), x1 - __bfloat162float(h1));
        }
        char* base = (char*)&smem[buf][0][0];
        const uint32_t off = (uint32_t)(ar * SST + ac) * 2;
        *(uint4*)(base + off)      = make_uint4(hi[0], hi[1], hi[2], hi[3]);
        *(uint4*)(base + off + 16) = make_uint4(hi[4], hi[5], hi[6], hi[7]);
        char* basel = (char*)&smem[buf][1][0];
        *(uint4*)(basel + off)      = make_uint4(lo[0], lo[1], lo[2], lo[3]);
        *(uint4*)(basel + off + 16) = make_uint4(lo[4], lo[5], lo[6], lo[7]);
    };
    auto issueB = [&](int buf, int k0) {
#pragma unroll
        for (int h = 0; h < 2; h++) {
            const int r = br_ + h * 64;
            const uint32_t soff = (uint32_t)(r * SST + bc8_) * 2;
            const uint32_t sb = sbase + buf * 4 * tilebytes + 2 * tilebytes + soff;
            const size_t boff = (size_t)(bn + r) * K + k0 + bc8_;
            cp16(sb, Bthi + boff);
            cp16(sb + tilebytes, Btlo + boff);
        }
        cp_commit();
    };

    const int nch = K >> 5;
    ldgA(0); issueB(0, 0); stsA(0);

    int buf = 0;
    for (int t = 0; t < nch; t++) {
        const bool has = (t + 1 < nch);
        if (has) {
            ldgA((t + 1) << 5);
            issueB(buf ^ 1, (t + 1) << 5);
            cp_wait<1>();
        } else {
            cp_wait<0>();
        }
        __syncthreads();

        const uint32_t sb = sbase + buf * 4 * tilebytes;
        const uint32_t sAh = sb, sAl = sb + tilebytes;
        const uint32_t sBh = sb + 2 * tilebytes, sBl = sb + 3 * tilebytes;

        const int arow = wm + (lane & 15);
        const int acol_off = (lane & 16) ? 8 : 0;
        const int brow = wn + (lane & 7) + ((lane & 16) ? 8 : 0);
        const int bcol_off = (lane & 8) ? 8 : 0;

#pragma unroll
        for (int ks = 0; ks < 2; ks++) {
            const int kb = ks * 16;
            uint32_t ah[2][4], al[2][4];
#pragma unroll
            for (int mt = 0; mt < 2; mt++) {
                const uint32_t aaddr = (uint32_t)(((arow + mt * 16) * SST) + kb + acol_off) * 2;
                ldmx4(ah[mt], sAh + aaddr);
                ldmx4(al[mt], sAl + aaddr);
            }
#pragma unroll
            for (int p = 0; p < 4; p++) {
                uint32_t bh[4], bl[4];
                const uint32_t baddr = (uint32_t)(((brow + p * 16) * SST) + kb + bcol_off) * 2;
                ldmx4(bh, sBh + baddr);
                ldmx4(bl, sBl + baddr);
#pragma unroll
                for (int sub = 0; sub < 2; sub++) {
                    const int nt = p * 2 + sub;
                    const uint32_t bh0 = bh[sub * 2], bh1 = bh[sub * 2 + 1];
                    const uint32_t bl0 = bl[sub * 2], bl1 = bl[sub * 2 + 1];
#pragma unroll
                    for (int mt = 0; mt < 2; mt++) {
                        mma16816(acc[mt][nt], ah[mt], bh0, bh1);
                        mma16816(acc[mt][nt], ah[mt], bl0, bl1);
                        mma16816(acc[mt][nt], al[mt], bh0, bh1);
                    }
                }
            }
        }
        __syncthreads();
        if (has) stsA(buf ^ 1);
        buf ^= 1;
    }

    // ---------------- epilogue ----------------
    float* Cf = (float*)Cv;
    __half* Ch = (__half*)Cv;
#pragma unroll
    for (int mt = 0; mt < 2; mt++) {
        const int r0 = bm + wm + mt * 16 + lr;
        const bool ok0 = r0 < M, ok1 = (r0 + 8) < M;
#pragma unroll
        for (int nt = 0; nt < 8; nt++) {
            const int col = bn + wn + nt * 8 + lc;
            float2 v0 = make_float2(acc[mt][nt][0], acc[mt][nt][1]);
            float2 v1 = make_float2(acc[mt][nt][2], acc[mt][nt][3]);
            if (FLAGS & 1) {
                float2 bb = *(const float2*)(bias + col);
                v0.x += bb.x; v0.y += bb.y; v1.x += bb.x; v1.y += bb.y;
            }
            if (FLAGS & 2) {
                v0.x = fmaxf(v0.x, 0.f); v0.y = fmaxf(v0.y, 0.f);
                v1.x = fmaxf(v1.x, 0.f); v1.y = fmaxf(v1.y, 0.f);
            }
            if (FLAGS & 64) {
                if (ok0) *(__half2*)(Ch + (size_t)r0 * N + col) = __floats2half2_rn(v0.x, v0.y);
                if (ok1) *(__half2*)(Ch + (size_t)(r0 + 8) * N + col) = __floats2half2_rn(v1.x, v1.y);
            } else {
                if (ok0) *(float2*)(Cf + (size_t)r0 * N + col) = v0;
                if (ok1) *(float2*)(Cf + (size_t)(r0 + 8) * N + col) = v1;
            }
            if (FLAGS & 8) {
                float s0 = (ok0 ? v0.x : 0.f) + (ok1 ? v1.x : 0.f);
                float s1 = (ok0 ? v0.y : 0.f) + (ok1 ? v1.y : 0.f);
                float q0 = (ok0 ? v0.x * v0.x : 0.f) + (ok1 ? v1.x * v1.x : 0.f);
                float q1 = (ok0 ? v0.y * v0.y : 0.f) + (ok1 ? v1.y * v1.y : 0.f);
                const int cc = wn + nt * 8 + lc;
                atomicAdd(&cs[cc], s0); atomicAdd(&cs[cc + 1], s1);
                atomicAdd(&cq[cc], q0); atomicAdd(&cq[cc + 1], q1);
            }
        }
    }
    if (FLAGS & 8) {
        __syncthreads();
        if (tid < 128) {
            ps[blockIdx.y * 128 + tid] = cs[tid];
            pq[blockIdx.y * 128 + tid] = cq[tid];
        }
    }
}

// ---------------- BatchNorm params (+ optional fold) ----------------
__global__ void bn_params_kernel(const float* __restrict__ gamma,
                                 const float* __restrict__ beta,
                                 const float* __restrict__ ps,
                                 const float* __restrict__ pq,
                                 int nb, int M,
                                 float* __restrict__ scale, float* __restrict__ shift,
                                 const float* __restrict__ wld_in,
                                 float* __restrict__ wldp, float* __restrict__ ldoff) {
    __shared__ double ss[4][128], sq[4][128];
    __shared__ float fsc[128], fsh[128], soff[4];
    int c = threadIdx.x & 127, part = threadIdx.x >> 7;
    double s = 0.0, q = 0.0;
    for (int b = part; b < nb; b += 4) { s += ps[b * 128 + c]; q += pq[b * 128 + c]; }
    ss[part][c] = s; sq[part][c] = q;
    if (threadIdx.x < 4) soff[threadIdx.x] = 0.f;
    __syncthreads();
    if (threadIdx.x < 128) {
        double S = ss[0][c] + ss[1][c] + ss[2][c] + ss[3][c];
        double Q = sq[0][c] + sq[1][c] + sq[2][c] + sq[3][c];
        double mu = S / M;
        double var = Q / M - mu * mu;
        float sc = gamma[c] * rsqrtf((float)var + 1e-5f);
        float sh = beta[c] - (float)mu * sc;
        scale[c] = sc; shift[c] = sh;
        fsc[c] = sc; fsh[c] = sh;
    }
    if (wld_in) {
        __syncthreads();
        int h = threadIdx.x >> 7;
        float w = wld_in[c * 4 + h];
        wldp[c * 4 + h] = fsc[c] * w;
        float p = fsh[c] * w;
#pragma unroll
        for (int off = 16; off > 0; off >>= 1)
            p += __shfl_xor_sync(0xffffffffu, p, off);
        if ((threadIdx.x & 31) == 0) atomicAdd(&soff[h], p);
        __syncthreads();
        if (threadIdx.x < 4) ldoff[threadIdx.x] = soff[threadIdx.x];
    }
}

// row dot: out[i][h] = sum_c A[i][c]*wldp[c][h] + ldoff[h]  (warp per row)
__global__ void ld_raw_kernel(const float* __restrict__ A, int M,
                              const float* __restrict__ wldp,
                              const float* __restrict__ ldoff,
                              float* __restrict__ ld_out) {
    int i = blockIdx.x * blockDim.x + threadIdx.x;
    if (i >= M * (CH / 4)) return;
    int c = (i & 31) * 4;
    float4 v = ((const float4*)A)[i];
    float4 w0 = ((const float4*)wldp)[c + 0];
    float4 w1 = ((const float4*)wldp)[c + 1];
    float4 w2 = ((const float4*)wldp)[c + 2];
    float4 w3 = ((const float4*)wldp)[c + 3];
    float p0 = v.x * w0.x + v.y * w1.x + v.z * w2.x + v.w * w3.x;
    float p1 = v.x * w0.y + v.y * w1.y + v.z * w2.y + v.w * w3.y;
    float p2 = v.x * w0.z + v.y * w1.z + v.z * w2.z + v.w * w3.z;
    float p3 = v.x * w0.w + v.y * w1.w + v.z * w2.w + v.w * w3.w;
#pragma unroll
    for (int off = 16; off > 0; off >>= 1) {
        p0 += __shfl_xor_sync(0xffffffffu, p0, off);
        p1 += __shfl_xor_sync(0xffffffffu, p1, off);
        p2 += __shfl_xor_sync(0xffffffffu, p2, off);
        p3 += __shfl_xor_sync(0xffffffffu, p3, off);
    }
    if ((i & 31) == 0)
        ((float4*)ld_out)[i >> 5] = make_float4(p0 + ldoff[0], p1 + ldoff[1],
                                                p2 + ldoff[2], p3 + ldoff[3]);
}

// ---------------- GAT pieces ----------------
__global__ void gat_edge_kernel(const int* __restrict__ src, const int* __restrict__ dst,
                                const float* __restrict__ ls, const float* __restrict__ ld,
                                float* __restrict__ denom, float* __restrict__ logits,
                                int E, int n_loop) {
    int e = blockIdx.x * blockDim.x + threadIdx.x;
    if (e >= E + n_loop) return;
    int s, d; bool mask;
    if (e < E) { s = src[e]; d = dst[e]; mask = (s != d); }
    else       { s = d = e - E; mask = true; }
    float4 a = ((const float4*)ls)[s];
    float4 b = ((const float4*)ld)[d];
    float p0 = mask ? expf(leaky(a.x + b.x)) : 0.f;
    float p1 = mask ? expf(leaky(a.y + b.y)) : 0.f;
    float p2 = mask ? expf(leaky(a.z + b.z)) : 0.f;
    float p3 = mask ? expf(leaky(a.w + b.w)) : 0.f;
    ((float4*)logits)[e] = make_float4(p0, p1, p2, p3);
    asm volatile("red.global.add.v4.f32 [%0], {%1, %2, %3, %4};"
                 :: "l"(denom + d * 4), "f"(p0), "f"(p1), "f"(p2), "f"(p3) : "memory");
}

// pass3: xs is fp16; each warp handles one edge, lane covers 4 output channels
__global__ void gat_pass3_kernel(const int* __restrict__ src, const int* __restrict__ dst,
                                 const float* __restrict__ logits,
                                 const float* __restrict__ denom,
                                 float* __restrict__ agg, int E, int n_loop) {
    int w = (blockIdx.x * blockDim.x + threadIdx.x) >> 5;
    int lane = threadIdx.x & 31;
    if (w >= E + n_loop) return;
    int s, d;
    if (w < E) { s = src[w]; d = dst[w]; }
    else       { s = d = w - E; }
    float4 P = ((const float4*)logits)[w];
    float4 D = ((const float4*)denom)[d];
    float a0 = 0.25f * P.x / (D.x > 0.f ? D.x : 1.f);
    float a1 = 0.25f * P.y / (D.y > 0.f ? D.y : 1.f);
    float a2 = 0.25f * P.z / (D.z > 0.f ? D.z : 1.f);
    float a3 = 0.25f * P.w / (D.w > 0.f ? D.w : 1.f);
    const __half* xr = g_xs + (size_t)s * 512 + lane * 4;
    float r0 = 0.f, r1 = 0.f, r2 = 0.f, r3 = 0.f;
    float ah[4] = {a0, a1, a2, a3};
#pragma unroll
    for (int h = 0; h < 4; h++) {
        uint2 u = *(const uint2*)(xr + h * 128);
        float2 f01 = __half22float2(*(const __half2*)&u.x);
        float2 f23 = __half22float2(*(const __half2*)&u.y);
        r0 += ah[h] * f01.x; r1 += ah[h] * f01.y;
        r2 += ah[h] * f23.x; r3 += ah[h] * f23.y;
    }
    float* out = agg + (size_t)d * CH + lane * 4;
    asm volatile("red.global.add.v4.f32 [%0], {%1, %2, %3, %4};"
                 :: "l"(out), "f"(r0), "f"(r1), "f"(r2), "f"(r3) : "memory");
}

// combine: gout = [BN(gin) if scale] + agg + bias; optional dual folds (ld2, ls2)
__global__ void combine_kernel(const float* __restrict__ gin, float* __restrict__ gout,
                               const float* __restrict__ bias,
                               const float* __restrict__ agg,
                               const float* __restrict__ scale,
                               const float* __restrict__ shift,
                               const float* __restrict__ wld, float* __restrict__ ld_out,
                               const float* __restrict__ wls, float* __restrict__ ls_out) {
    int i = blockIdx.x * blockDim.x + threadIdx.x;
    if (i >= NGENE * 32) return;
    int c = (i & 31) * 4;
    float4 v = ((const float4*)gin)[i];
    if (scale) {
        v.x = v.x * scale[c + 0] + shift[c + 0];
        v.y = v.y * scale[c + 1] + shift[c + 1];
        v.z = v.z * scale[c + 2] + shift[c + 2];
        v.w = v.w * scale[c + 3] + shift[c + 3];
    }
    float4 ag = ((const float4*)agg)[i];
    v.x += ag.x + bias[c + 0];
    v.y += ag.y + bias[c + 1];
    v.z += ag.z + bias[c + 2];
    v.w += ag.w + bias[c + 3];
    ((float4*)gout)[i] = v;
    if (wld) {
        float4 w0 = ((const float4*)wld)[c + 0];
        float4 w1 = ((const float4*)wld)[c + 1];
        float4 w2 = ((const float4*)wld)[c + 2];
        float4 w3 = ((const float4*)wld)[c + 3];
        float p0 = v.x * w0.x + v.y * w1.x + v.z * w2.x + v.w * w3.x;
        float p1 = v.x * w0.y + v.y * w1.y + v.z * w2.y + v.w * w3.y;
        float p2 = v.x * w0.z + v.y * w1.z + v.z * w2.z + v.w * w3.z;
        float p3 = v.x * w0.w + v.y * w1.w + v.z * w2.w + v.w * w3.w;
        float4 u0 = ((const float4*)wls)[c + 0];
        float4 u1 = ((const float4*)wls)[c + 1];
        float4 u2 = ((const float4*)wls)[c + 2];
        float4 u3 = ((const float4*)wls)[c + 3];
        float q0 = v.x * u0.x + v.y * u1.x + v.z * u2.x + v.w * u3.x;
        float q1 = v.x * u0.y + v.y * u1.y + v.z * u2.y + v.w * u3.y;
        float q2 = v.x * u0.z + v.y * u1.z + v.z * u2.z + v.w * u3.z;
        float q3 = v.x * u0.w + v.y * u1.w + v.z * u2.w + v.w * u3.w;
#pragma unroll
        for (int off = 16; off > 0; off >>= 1) {
            p0 += __shfl_xor_sync(0xffffffffu, p0, off);
            p1 += __shfl_xor_sync(0xffffffffu, p1, off);
            p2 += __shfl_xor_sync(0xffffffffu, p2, off);
            p3 += __shfl_xor_sync(0xffffffffu, p3, off);
            q0 += __shfl_xor_sync(0xffffffffu, q0, off);
            q1 += __shfl_xor_sync(0xffffffffu, q1, off);
            q2 += __shfl_xor_sync(0xffffffffu, q2, off);
            q3 += __shfl_xor_sync(0xffffffffu, q3, off);
        }
        if ((i & 31) == 0) {
            ((float4*)ld_out)[i >> 5] = make_float4(p0, p1, p2, p3);
            ((float4*)ls_out)[i >> 5] = make_float4(q0, q1, q2, q3);
        }
    }
}

// ---------------- launch ----------------
#define SYM(p, s) cudaGetSymbolAddress((void**)&p, s)

extern "C" void kernel_launch(void* const* d_in, const int* in_sizes, int n_in,
                              void* d_out, int out_size) {
    const float* x_gene = (const float*)d_in[0];
    const float* x_dis  = (const float*)d_in[1];
    const int* e1_src = (const int*)d_in[2];
    const int* e1_dst = (const int*)d_in[3];
    const int* e2_src = (const int*)d_in[4];
    const int* e2_dst = (const int*)d_in[5];
    const float* Wg = (const float*)d_in[6];
    const float* bg = (const float*)d_in[7];
    const float* gg = (const float*)d_in[8];
    const float* betag = (const float*)d_in[9];
    const float* Wd = (const float*)d_in[10];
    const float* bd = (const float*)d_in[11];
    const float* gd = (const float*)d_in[12];
    const float* betad = (const float*)d_in[13];
    const float* W1s = (const float*)d_in[14];
    const float* W1d = (const float*)d_in[15];
    const float* a1s = (const float*)d_in[16];
    const float* a1d = (const float*)d_in[17];
    const float* b1  = (const float*)d_in[18];
    const float* W2s = (const float*)d_in[19];
    const float* W2d = (const float*)d_in[20];
    const float* a2s = (const float*)d_in[21];
    const float* a2d = (const float*)d_in[22];
    const float* b2  = (const float*)d_in[23];

    float* out_gene = (float*)d_out;
    float* out_dis  = (float*)d_out + (size_t)NGENE * CH;

    __half* xs;
    float *geneA, *disA, *zb1, *zb2, *ls1, *ls2, *ld1, *ld2, *lg1, *lg2;
    float *wld1, *wld2, *wls1, *wls2, *wldpg, *ldoffg, *wlspd, *lsoffd;
    float *psG, *pqG, *psD, *pqD, *scG, *shG, *scD, *shD;
    __nv_bfloat16 *bt1_h, *bt1_l, *bt2_h, *bt2_l, *btg_h, *btg_l, *btd_h, *btd_l;
    SYM(xs, g_xs); SYM(geneA, g_geneA); SYM(disA, g_disA);
    SYM(zb1, g_zb1); SYM(zb2, g_zb2);
    SYM(ls1, g_ls1); SYM(ls2, g_ls2); SYM(ld1, g_ld1); SYM(ld2, g_ld2);
    SYM(lg1, g_logits1); SYM(lg2, g_logits2);
    SYM(wld1, g_wld1); SYM(wld2, g_wld2); SYM(wls1, g_wls1); SYM(wls2, g_wls2);
    SYM(wldpg, g_wldpg); SYM(ldoffg, g_ldoffg); SYM(wlspd, g_wlspd); SYM(lsoffd, g_lsoffd);
    SYM(psG, g_psG); SYM(pqG, g_pqG); SYM(psD, g_psD); SYM(pqD, g_pqD);
    SYM(scG, g_scaleG); SYM(shG, g_shiftG); SYM(scD, g_scaleD); SYM(shD, g_shiftD);
    SYM(btg_h, g_btg_hi); SYM(btg_l, g_btg_lo); SYM(btd_h, g_btd_hi); SYM(btd_l, g_btd_lo);
    SYM(bt1_h, g_bt1_hi); SYM(bt1_l, g_bt1_lo); SYM(bt2_h, g_bt2_hi); SYM(bt2_l, g_bt2_lo);

    float* agg1 = zb1;  float* dn1 = zb1 + (size_t)NGENE * CH;
    float* agg2 = zb2;  float* dn2 = zb2 + (size_t)NGENE * CH;

    cudaStream_t s1, s2;
    cudaStreamCreateWithFlags(&s1, cudaStreamNonBlocking);
    cudaStreamCreateWithFlags(&s2, cudaStreamNonBlocking);
    cudaEvent_t e0, e_prep, e_ls1, e_xs1, e_z1, e_z2, e_c1, e_e2;
    cudaEventCreateWithFlags(&e0, cudaEventDisableTiming);
    cudaEventCreateWithFlags(&e_prep, cudaEventDisableTiming);
    cudaEventCreateWithFlags(&e_ls1, cudaEventDisableTiming);
    cudaEventCreateWithFlags(&e_xs1, cudaEventDisableTiming);
    cudaEventCreateWithFlags(&e_z1, cudaEventDisableTiming);
    cudaEventCreateWithFlags(&e_z2, cudaEventDisableTiming);
    cudaEventCreateWithFlags(&e_c1, cudaEventDisableTiming);
    cudaEventCreateWithFlags(&e_e2, cudaEventDisableTiming);

    cudaEventRecord(e0, 0);
    cudaStreamWaitEvent(s1, e0, 0);
    cudaStreamWaitEvent(s2, e0, 0);

    const int GY_G = (NGENE + 127) / 128;   // 391
    const int GY_D = (NDIS + 127) / 128;    // 196

    // ---- s2: single prep kernel + zeroing ----
    prep_kernel<<<1152, 256, 0, s2>>>(Wg, Wd, W1s, W2s, W1d, a1d, W2d, a2d, a1s, a2s);
    cudaEventRecord(e_prep, s2);
    cudaMemsetAsync(zb1, 0, (size_t)NGENE * (CH + 4) * sizeof(float), s2);
    cudaEventRecord(e_z1, s2);
    cudaMemsetAsync(zb2, 0, (size_t)NGENE * (CH + 4) * sizeof(float), s2);
    cudaEventRecord(e_z2, s2);

    // ---- s1: dis encode -> ls1 -> xs1 GEMM (fp16 C) ----
    cudaStreamWaitEvent(s1, e_prep, 0);
    gemm_mma_kernel<1 | 2 | 8><<<dim3(1, GY_D), 256, 0, s1>>>(
        x_dis, btd_h, btd_l, bd, psD, pqD, nullptr, nullptr, nullptr,
        disA, NDIS, CH, FDIS);
    bn_params_kernel<<<1, 512, 0, s1>>>(gd, betad, psD, pqD, GY_D, NDIS, scD, shD,
                                        wls1, wlspd, lsoffd);
    ld_raw_kernel<<<(NDIS * 32 + 255) / 256, 256, 0, s1>>>(disA, NDIS, wlspd, lsoffd, ls1);
    cudaEventRecord(e_ls1, s1);
    gemm_mma_kernel<32 | 64><<<dim3(4, GY_D), 256, 0, s1>>>(
        disA, bt1_h, bt1_l, nullptr, nullptr, nullptr, scD, shD, out_dis,
        xs, NDIS, 512, CH);
    cudaEventRecord(e_xs1, s1);

    // ---- s0: gene encode -> ld1 ----
    cudaStreamWaitEvent(0, e_prep, 0);
    gemm_mma_kernel<1 | 2 | 8><<<dim3(1, GY_G), 256>>>(
        x_gene, btg_h, btg_l, bg, psG, pqG, nullptr, nullptr, nullptr,
        geneA, NGENE, CH, FGENE);
    bn_params_kernel<<<1, 512>>>(gg, betag, psG, pqG, GY_G, NGENE, scG, shG,
                                 wld1, wldpg, ldoffg);
    ld_raw_kernel<<<(NGENE * 32 + 255) / 256, 256>>>(geneA, NGENE, wldpg, ldoffg, ld1);

    // ---- relation 1 on s0 ----
    cudaStreamWaitEvent(0, e_ls1, 0);
    cudaStreamWaitEvent(0, e_z1, 0);
    {
        const int E = NE, n_loop = NDIS, ET = E + n_loop;
        gat_edge_kernel<<<(ET + 255) / 256, 256>>>(e1_src, e1_dst, ls1, ld1, dn1, lg1, E, n_loop);
        cudaStreamWaitEvent(0, e_xs1, 0);
        gat_pass3_kernel<<<(ET + 7) / 8, 256>>>(e1_src, e1_dst, lg1, dn1, agg1, E, n_loop);
    }
    // combine1: BN(geneA)+agg1+b1 -> geneA, dual fold -> ld2, ls2
    combine_kernel<<<(NGENE * 32 + 255) / 256, 256>>>(geneA, geneA, b1, agg1,
                                                      scG, shG, wld2, ld2, wls2, ls2);
    cudaEventRecord(e_c1, 0);

    // ---- relation 2: xs2 GEMM (fp16 C) on s0, edge2 concurrently on s1 ----
    gemm_mma_kernel<64><<<dim3(4, GY_G), 256>>>(
        geneA, bt2_h, bt2_l, nullptr, nullptr, nullptr, nullptr, nullptr, nullptr,
        xs, NGENE, 512, CH);
    cudaStreamWaitEvent(s1, e_c1, 0);
    cudaStreamWaitEvent(s1, e_z2, 0);
    {
        const int E = NE, n_loop = NGENE, ET = E + n_loop;
        gat_edge_kernel<<<(ET + 255) / 256, 256, 0, s1>>>(e2_src, e2_dst, ls2, ld2, dn2, lg2,
                                                          E, n_loop);
        cudaEventRecord(e_e2, s1);
        cudaStreamWaitEvent(0, e_e2, 0);
        gat_pass3_kernel<<<(ET + 7) / 8, 256>>>(e2_src, e2_dst, lg2, dn2, agg2, E, n_loop);
    }
    combine_kernel<<<(NGENE * 32 + 255) / 256, 256>>>(geneA, out_gene, b2, agg2,
                                                      nullptr, nullptr, nullptr, nullptr,
                                                      nullptr, nullptr);

    cudaEventDestroy(e0);
    cudaEventDestroy(e_prep);
    cudaEventDestroy(e_ls1);
    cudaEventDestroy(e_xs1);
    cudaEventDestroy(e_z1);
    cudaEventDestroy(e_z2);
    cudaEventDestroy(e_c1);
    cudaEventDestroy(e_e2);
    cudaStreamDestroy(s1);
    cudaStreamDestroy(s2);
}

// round 15
// speedup vs baseline: 1.1287x; 1.0618x over previous
#include <cuda_runtime.h>
#include <cuda_bf16.h>
#include <cuda_fp16.h>
#include <math.h>
#include <cstdint>

#define NGENE 50000
#define NDIS  25000
#define FGENE 512
#define FDIS  256
#define CH    128
#define NE    150000

// ---------------- scratch ----------------
__device__ __half g_xs[(size_t)NGENE * 512];         // fp16 value tensor
__device__ float  g_geneA[(size_t)NGENE * CH];
__device__ float  g_disA[(size_t)NDIS * CH];
__device__ float  g_zb1[(size_t)NGENE * (CH + 4)];   // agg1 | denom1
__device__ float  g_zb2[(size_t)NGENE * (CH + 4)];   // agg2 | denom2
__device__ float  g_ls1[NGENE * 4];
__device__ float  g_ls2[NGENE * 4];
__device__ float  g_ld1[NGENE * 4];
__device__ float  g_ld2[NGENE * 4];
__device__ float  g_logits1[(NE + NDIS) * 4];
__device__ float  g_logits2[(NE + NGENE) * 4];
__device__ float  g_wld1[512], g_wld2[512], g_wls1[512], g_wls2[512];
__device__ float  g_wldpg[512], g_ldoffg[4];
__device__ float  g_wlspd[512], g_lsoffd[4];
__device__ float  g_psG[400 * 128], g_pqG[400 * 128];
__device__ float  g_psD[400 * 128], g_pqD[400 * 128];
__device__ float  g_scaleG[CH], g_shiftG[CH], g_scaleD[CH], g_shiftD[CH];
__device__ __align__(256) __nv_bfloat16 g_btg_hi[512 * 128], g_btg_lo[512 * 128];
__device__ __align__(256) __nv_bfloat16 g_btd_hi[512 * 128], g_btd_lo[512 * 128];
__device__ __align__(256) __half g_bt1f16[512 * 128];   // fp16 single for xs1 B
__device__ __align__(256) __half g_bt2f16[512 * 128];   // fp16 single for xs2 B

// ---------------- small helpers ----------------
__device__ __forceinline__ float leaky(float x) { return x > 0.f ? x : 0.2f * x; }
__device__ __forceinline__ uint32_t smem_u32(const void* p) {
    uint32_t a;
    asm("{ .reg .u64 t; cvta.to.shared.u64 t, %1; cvt.u32.u64 %0, t; }" : "=r"(a) : "l"(p));
    return a;
}
__device__ __forceinline__ void mma16816(float* c, const uint32_t* a,
                                         uint32_t b0, uint32_t b1) {
    asm volatile("mma.sync.aligned.m16n8k16.row.col.f32.bf16.bf16.f32 "
                 "{%0,%1,%2,%3}, {%4,%5,%6,%7}, {%8,%9}, {%0,%1,%2,%3};"
                 : "+f"(c[0]), "+f"(c[1]), "+f"(c[2]), "+f"(c[3])
                 : "r"(a[0]), "r"(a[1]), "r"(a[2]), "r"(a[3]), "r"(b0), "r"(b1));
}
__device__ __forceinline__ void mma16816h(float* c, const uint32_t* a,
                                          uint32_t b0, uint32_t b1) {
    asm volatile("mma.sync.aligned.m16n8k16.row.col.f32.f16.f16.f32 "
                 "{%0,%1,%2,%3}, {%4,%5,%6,%7}, {%8,%9}, {%0,%1,%2,%3};"
                 : "+f"(c[0]), "+f"(c[1]), "+f"(c[2]), "+f"(c[3])
                 : "r"(a[0]), "r"(a[1]), "r"(a[2]), "r"(a[3]), "r"(b0), "r"(b1));
}
__device__ __forceinline__ void ldmx4(uint32_t* r, uint32_t addr) {
    asm volatile("ldmatrix.sync.aligned.m8n8.x4.shared.b16 {%0,%1,%2,%3}, [%4];"
                 : "=r"(r[0]), "=r"(r[1]), "=r"(r[2]), "=r"(r[3]) : "r"(addr));
}
__device__ __forceinline__ void cp16(uint32_t saddr, const void* g) {
    asm volatile("cp.async.cg.shared.global [%0], [%1], 16;" :: "r"(saddr), "l"(g));
}
__device__ __forceinline__ void cp_commit() {
    asm volatile("cp.async.commit_group;" ::: "memory");
}
template <int N_>
__device__ __forceinline__ void cp_wait() {
    asm volatile("cp.async.wait_group %0;" :: "n"(N_) : "memory");
}
__device__ __forceinline__ uint32_t pack_bf2(float x, float y) {
    __nv_bfloat162 t(__float2bfloat16(x), __float2bfloat16(y));
    return *(uint32_t*)&t;
}
__device__ __forceinline__ uint32_t pack_hf2(float x, float y) {
    __half2 t = __floats2half2_rn(x, y);
    return *(uint32_t*)&t;
}

// ---------------- batched prep ----------------
__device__ __forceinline__ void split_body(const float* B, __nv_bfloat16* thi,
                                           __nv_bfloat16* tlo, int K, int N,
                                           int idx, int total) {
    if (idx >= total) return;
    int k = idx / N, n = idx % N;
    float v = B[idx];
    __nv_bfloat16 h = __float2bfloat16(v);
    thi[(size_t)n * K + k] = h;
    tlo[(size_t)n * K + k] = __float2bfloat16(v - __bfloat162float(h));
}
__device__ __forceinline__ void half_body(const float* B, __half* t, int K, int N,
                                          int idx, int total) {
    if (idx >= total) return;
    int k = idx / N, n = idx % N;
    t[(size_t)n * K + k] = __float2half(B[idx]);
}
__device__ __forceinline__ void fold_body(const float* W, const float* a,
                                          float* out, int w, int lane) {
    int k = w >> 2, h = w & 3;
    float4 x = ((const float4*)(W + (size_t)k * 512 + h * 128))[lane];
    float4 y = ((const float4*)(a + h * 128))[lane];
    float s = x.x * y.x + x.y * y.y + x.z * y.z + x.w * y.w;
#pragma unroll
    for (int off = 16; off > 0; off >>= 1)
        s += __shfl_xor_sync(0xffffffffu, s, off);
    if (lane == 0) out[k * 4 + h] = s;
}

__global__ void prep_kernel(const float* __restrict__ Wg, const float* __restrict__ Wd,
                            const float* __restrict__ W1s, const float* __restrict__ W2s,
                            const float* __restrict__ W1d, const float* __restrict__ a1d,
                            const float* __restrict__ W2d, const float* __restrict__ a2d,
                            const float* __restrict__ a1s, const float* __restrict__ a2s) {
    const int b = blockIdx.x, tid = threadIdx.x;
    if (b < 256) {
        half_body(W1s, g_bt1f16, CH, 512, b * 256 + tid, CH * 512);
    } else if (b < 512) {
        half_body(W2s, g_bt2f16, CH, 512, (b - 256) * 256 + tid, CH * 512);
    } else if (b < 768) {
        split_body(Wg, g_btg_hi, g_btg_lo, FGENE, CH, (b - 512) * 256 + tid, FGENE * CH);
    } else if (b < 896) {
        split_body(Wd, g_btd_hi, g_btd_lo, FDIS, CH, (b - 768) * 256 + tid, FDIS * CH);
    } else if (b < 960) {
        fold_body(W1d, a1d, g_wld1, (b - 896) * 8 + (tid >> 5), tid & 31);
    } else if (b < 1024) {
        fold_body(W2d, a2d, g_wld2, (b - 960) * 8 + (tid >> 5), tid & 31);
    } else if (b < 1088) {
        fold_body(W1s, a1s, g_wls1, (b - 1024) * 8 + (tid >> 5), tid & 31);
    } else {
        fold_body(W2s, a2s, g_wls2, (b - 1088) * 8 + (tid >> 5), tid & 31);
    }
}

// ---------------- GEMM (templated on FLAGS) ----------------
// FLAGS: 1=bias, 2=relu, 8=colsum partials, 32=BN A-transform (bx==0 -> Aout),
//        64=store C fp16, 128=single-term fp16 mode (A conv fp16, B fp16)
#define SST 40

template <int FLAGS>
__global__ __launch_bounds__(256, 2)
void gemm_mma_kernel(const float* __restrict__ A,
                     const void* __restrict__ Bthi_v,
                     const __nv_bfloat16* __restrict__ Btlo,
                     const float* __restrict__ bias,
                     float* __restrict__ ps, float* __restrict__ pq,
                     const float* __restrict__ ascale, const float* __restrict__ ashift,
                     float* __restrict__ Aout,
                     void* __restrict__ Cv, int M, int N, int K)
{
    constexpr bool F16 = (FLAGS & 128) != 0;
    __shared__ __align__(16) __nv_bfloat16 smem[2][4][128 * SST];
    __shared__ float cs[128], cq[128];

    const __nv_bfloat16* Bthi = (const __nv_bfloat16*)Bthi_v;

    const int tid = threadIdx.x, wid = tid >> 5, lane = tid & 31;
    const int bm = blockIdx.y * 128, bn = blockIdx.x * 128;
    const int wm = (wid & 3) * 32, wn = (wid >> 2) * 64;
    const int lr = lane >> 2, lc = (lane & 3) * 2;
    const uint32_t sbase = smem_u32(&smem[0][0][0]);
    const uint32_t tilebytes = 128 * SST * 2;

    if ((FLAGS & 8) && tid < 128) { cs[tid] = 0.f; cq[tid] = 0.f; }

    float acc[2][8][4];
#pragma unroll
    for (int mt = 0; mt < 2; mt++)
#pragma unroll
        for (int nt = 0; nt < 8; nt++)
#pragma unroll
            for (int j = 0; j < 4; j++) acc[mt][nt][j] = 0.f;

    const int br_ = tid >> 2, bc8_ = (tid & 3) * 8;
    const int ar = tid >> 1, ac = (tid & 1) * 16;
    const bool arow_ok = (bm + ar < M);
    const int agr = arow_ok ? (bm + ar) : (M - 1);

    float av[16];

    auto ldgA = [&](int k0) {
        const float4* p = (const float4*)(A + (size_t)agr * K + k0 + ac);
        float4 v0 = p[0], v1 = p[1], v2 = p[2], v3 = p[3];
        av[0] = v0.x; av[1] = v0.y; av[2] = v0.z; av[3] = v0.w;
        av[4] = v1.x; av[5] = v1.y; av[6] = v1.z; av[7] = v1.w;
        av[8] = v2.x; av[9] = v2.y; av[10] = v2.z; av[11] = v2.w;
        av[12] = v3.x; av[13] = v3.y; av[14] = v3.z; av[15] = v3.w;
        if (FLAGS & 32) {
            const float4* sc = (const float4*)(ascale + k0 + ac);
            const float4* sh = (const float4*)(ashift + k0 + ac);
#pragma unroll
            for (int q = 0; q < 4; q++) {
                float4 s4 = sc[q], h4 = sh[q];
                av[4 * q + 0] = av[4 * q + 0] * s4.x + h4.x;
                av[4 * q + 1] = av[4 * q + 1] * s4.y + h4.y;
                av[4 * q + 2] = av[4 * q + 2] * s4.z + h4.z;
                av[4 * q + 3] = av[4 * q + 3] * s4.w + h4.w;
            }
            if (blockIdx.x == 0 && arow_ok) {
                float4* o = (float4*)(Aout + (size_t)(bm + ar) * K + k0 + ac);
                o[0] = make_float4(av[0], av[1], av[2], av[3]);
                o[1] = make_float4(av[4], av[5], av[6], av[7]);
                o[2] = make_float4(av[8], av[9], av[10], av[11]);
                o[3] = make_float4(av[12], av[13], av[14], av[15]);
            }
        }
    };
    auto stsA = [&](int buf) {
        const uint32_t off = (uint32_t)(ar * SST + ac) * 2;
        if (F16) {
            uint32_t hi[8];
#pragma unroll
            for (int j = 0; j < 8; j++) hi[j] = pack_hf2(av[2 * j], av[2 * j + 1]);
            char* base = (char*)&smem[buf][0][0];
            *(uint4*)(base + off)      = make_uint4(hi[0], hi[1], hi[2], hi[3]);
            *(uint4*)(base + off + 16) = make_uint4(hi[4], hi[5], hi[6], hi[7]);
        } else {
            uint32_t hi[8], lo[8];
#pragma unroll
            for (int j = 0; j < 8; j++) {
                float x0 = av[2 * j], x1 = av[2 * j + 1];
                __nv_bfloat16 h0 = __float2bfloat16(x0), h1 = __float2bfloat16(x1);
                hi[j] = pack_bf2(x0, x1);
                lo[j] = pack_bf2(x0 - __bfloat162float(h0), x1 - __bfloat162float(h1));
            }
            char* base = (char*)&smem[buf][0][0];
            *(uint4*)(base + off)      = make_uint4(hi[0], hi[1], hi[2], hi[3]);
            *(uint4*)(base + off + 16) = make_uint4(hi[4], hi[5], hi[6], hi[7]);
            char* basel = (char*)&smem[buf][1][0];
            *(uint4*)(basel + off)      = make_uint4(lo[0], lo[1], lo[2], lo[3]);
            *(uint4*)(basel + off + 16) = make_uint4(lo[4], lo[5], lo[6], lo[7]);
        }
    };
    auto issueB = [&](int buf, int k0) {
#pragma unroll
        for (int h = 0; h < 2; h++) {
            const int r = br_ + h * 64;
            const uint32_t soff = (uint32_t)(r * SST + bc8_) * 2;
            const uint32_t sb = sbase + buf * 4 * tilebytes + 2 * tilebytes + soff;
            const size_t boff = (size_t)(bn + r) * K + k0 + bc8_;
            cp16(sb, Bthi + boff);
            if (!F16) cp16(sb + tilebytes, Btlo + boff);
        }
        cp_commit();
    };

    const int nch = K >> 5;
    ldgA(0); issueB(0, 0); stsA(0);

    int buf = 0;
    for (int t = 0; t < nch; t++) {
        const bool has = (t + 1 < nch);
        if (has) {
            ldgA((t + 1) << 5);
            issueB(buf ^ 1, (t + 1) << 5);
            cp_wait<1>();
        } else {
            cp_wait<0>();
        }
        __syncthreads();

        const uint32_t sb = sbase + buf * 4 * tilebytes;
        const uint32_t sAh = sb, sAl = sb + tilebytes;
        const uint32_t sBh = sb + 2 * tilebytes, sBl = sb + 3 * tilebytes;

        const int arow = wm + (lane & 15);
        const int acol_off = (lane & 16) ? 8 : 0;
        const int brow = wn + (lane & 7) + ((lane & 16) ? 8 : 0);
        const int bcol_off = (lane & 8) ? 8 : 0;

#pragma unroll
        for (int ks = 0; ks < 2; ks++) {
            const int kb = ks * 16;
            uint32_t ah[2][4], al[2][4];
#pragma unroll
            for (int mt = 0; mt < 2; mt++) {
                const uint32_t aaddr = (uint32_t)(((arow + mt * 16) * SST) + kb + acol_off) * 2;
                ldmx4(ah[mt], sAh + aaddr);
                if (!F16) ldmx4(al[mt], sAl + aaddr);
            }
#pragma unroll
            for (int p = 0; p < 4; p++) {
                uint32_t bh[4], bl[4];
                const uint32_t baddr = (uint32_t)(((brow + p * 16) * SST) + kb + bcol_off) * 2;
                ldmx4(bh, sBh + baddr);
                if (!F16) ldmx4(bl, sBl + baddr);
#pragma unroll
                for (int sub = 0; sub < 2; sub++) {
                    const int nt = p * 2 + sub;
                    const uint32_t bh0 = bh[sub * 2], bh1 = bh[sub * 2 + 1];
#pragma unroll
                    for (int mt = 0; mt < 2; mt++) {
                        if (F16) {
                            mma16816h(acc[mt][nt], ah[mt], bh0, bh1);
                        } else {
                            const uint32_t bl0 = bl[sub * 2], bl1 = bl[sub * 2 + 1];
                            mma16816(acc[mt][nt], ah[mt], bh0, bh1);
                            mma16816(acc[mt][nt], ah[mt], bl0, bl1);
                            mma16816(acc[mt][nt], al[mt], bh0, bh1);
                        }
                    }
                }
            }
        }
        __syncthreads();
        if (has) stsA(buf ^ 1);
        buf ^= 1;
    }

    // ---------------- epilogue ----------------
    float* Cf = (float*)Cv;
    __half* Ch = (__half*)Cv;
#pragma unroll
    for (int mt = 0; mt < 2; mt++) {
        const int r0 = bm + wm + mt * 16 + lr;
        const bool ok0 = r0 < M, ok1 = (r0 + 8) < M;
#pragma unroll
        for (int nt = 0; nt < 8; nt++) {
            const int col = bn + wn + nt * 8 + lc;
            float2 v0 = make_float2(acc[mt][nt][0], acc[mt][nt][1]);
            float2 v1 = make_float2(acc[mt][nt][2], acc[mt][nt][3]);
            if (FLAGS & 1) {
                float2 bb = *(const float2*)(bias + col);
                v0.x += bb.x; v0.y += bb.y; v1.x += bb.x; v1.y += bb.y;
            }
            if (FLAGS & 2) {
                v0.x = fmaxf(v0.x, 0.f); v0.y = fmaxf(v0.y, 0.f);
                v1.x = fmaxf(v1.x, 0.f); v1.y = fmaxf(v1.y, 0.f);
            }
            if (FLAGS & 64) {
                if (ok0) *(__half2*)(Ch + (size_t)r0 * N + col) = __floats2half2_rn(v0.x, v0.y);
                if (ok1) *(__half2*)(Ch + (size_t)(r0 + 8) * N + col) = __floats2half2_rn(v1.x, v1.y);
            } else {
                if (ok0) *(float2*)(Cf + (size_t)r0 * N + col) = v0;
                if (ok1) *(float2*)(Cf + (size_t)(r0 + 8) * N + col) = v1;
            }
            if (FLAGS & 8) {
                float s0 = (ok0 ? v0.x : 0.f) + (ok1 ? v1.x : 0.f);
                float s1 = (ok0 ? v0.y : 0.f) + (ok1 ? v1.y : 0.f);
                float q0 = (ok0 ? v0.x * v0.x : 0.f) + (ok1 ? v1.x * v1.x : 0.f);
                float q1 = (ok0 ? v0.y * v0.y : 0.f) + (ok1 ? v1.y * v1.y : 0.f);
                const int cc = wn + nt * 8 + lc;
                atomicAdd(&cs[cc], s0); atomicAdd(&cs[cc + 1], s1);
                atomicAdd(&cq[cc], q0); atomicAdd(&cq[cc + 1], q1);
            }
        }
    }
    if (FLAGS & 8) {
        __syncthreads();
        if (tid < 128) {
            ps[blockIdx.y * 128 + tid] = cs[tid];
            pq[blockIdx.y * 128 + tid] = cq[tid];
        }
    }
}

// ---------------- BatchNorm params (+ optional fold) ----------------
__global__ void bn_params_kernel(const float* __restrict__ gamma,
                                 const float* __restrict__ beta,
                                 const float* __restrict__ ps,
                                 const float* __restrict__ pq,
                                 int nb, int M,
                                 float* __restrict__ scale, float* __restrict__ shift,
                                 const float* __restrict__ wld_in,
                                 float* __restrict__ wldp, float* __restrict__ ldoff) {
    __shared__ double ss[4][128], sq[4][128];
    __shared__ float fsc[128], fsh[128], soff[4];
    int c = threadIdx.x & 127, part = threadIdx.x >> 7;
    double s = 0.0, q = 0.0;
    for (int b = part; b < nb; b += 4) { s += ps[b * 128 + c]; q += pq[b * 128 + c]; }
    ss[part][c] = s; sq[part][c] = q;
    if (threadIdx.x < 4) soff[threadIdx.x] = 0.f;
    __syncthreads();
    if (threadIdx.x < 128) {
        double S = ss[0][c] + ss[1][c] + ss[2][c] + ss[3][c];
        double Q = sq[0][c] + sq[1][c] + sq[2][c] + sq[3][c];
        double mu = S / M;
        double var = Q / M - mu * mu;
        float sc = gamma[c] * rsqrtf((float)var + 1e-5f);
        float sh = beta[c] - (float)mu * sc;
        scale[c] = sc; shift[c] = sh;
        fsc[c] = sc; fsh[c] = sh;
    }
    if (wld_in) {
        __syncthreads();
        int h = threadIdx.x >> 7;
        float w = wld_in[c * 4 + h];
        wldp[c * 4 + h] = fsc[c] * w;
        float p = fsh[c] * w;
#pragma unroll
        for (int off = 16; off > 0; off >>= 1)
            p += __shfl_xor_sync(0xffffffffu, p, off);
        if ((threadIdx.x & 31) == 0) atomicAdd(&soff[h], p);
        __syncthreads();
        if (threadIdx.x < 4) ldoff[threadIdx.x] = soff[threadIdx.x];
    }
}

// row dot: out[i][h] = sum_c A[i][c]*wldp[c][h] + ldoff[h]  (warp per row)
__global__ void ld_raw_kernel(const float* __restrict__ A, int M,
                              const float* __restrict__ wldp,
                              const float* __restrict__ ldoff,
                              float* __restrict__ ld_out) {
    int i = blockIdx.x * blockDim.x + threadIdx.x;
    if (i >= M * (CH / 4)) return;
    int c = (i & 31) * 4;
    float4 v = ((const float4*)A)[i];
    float4 w0 = ((const float4*)wldp)[c + 0];
    float4 w1 = ((const float4*)wldp)[c + 1];
    float4 w2 = ((const float4*)wldp)[c + 2];
    float4 w3 = ((const float4*)wldp)[c + 3];
    float p0 = v.x * w0.x + v.y * w1.x + v.z * w2.x + v.w * w3.x;
    float p1 = v.x * w0.y + v.y * w1.y + v.z * w2.y + v.w * w3.y;
    float p2 = v.x * w0.z + v.y * w1.z + v.z * w2.z + v.w * w3.z;
    float p3 = v.x * w0.w + v.y * w1.w + v.z * w2.w + v.w * w3.w;
#pragma unroll
    for (int off = 16; off > 0; off >>= 1) {
        p0 += __shfl_xor_sync(0xffffffffu, p0, off);
        p1 += __shfl_xor_sync(0xffffffffu, p1, off);
        p2 += __shfl_xor_sync(0xffffffffu, p2, off);
        p3 += __shfl_xor_sync(0xffffffffu, p3, off);
    }
    if ((i & 31) == 0)
        ((float4*)ld_out)[i >> 5] = make_float4(p0 + ldoff[0], p1 + ldoff[1],
                                                p2 + ldoff[2], p3 + ldoff[3]);
}

// ---------------- GAT pieces ----------------
__global__ void gat_edge_kernel(const int* __restrict__ src, const int* __restrict__ dst,
                                const float* __restrict__ ls, const float* __restrict__ ld,
                                float* __restrict__ denom, float* __restrict__ logits,
                                int E, int n_loop) {
    int e = blockIdx.x * blockDim.x + threadIdx.x;
    if (e >= E + n_loop) return;
    int s, d; bool mask;
    if (e < E) { s = src[e]; d = dst[e]; mask = (s != d); }
    else       { s = d = e - E; mask = true; }
    float4 a = ((const float4*)ls)[s];
    float4 b = ((const float4*)ld)[d];
    float p0 = mask ? expf(leaky(a.x + b.x)) : 0.f;
    float p1 = mask ? expf(leaky(a.y + b.y)) : 0.f;
    float p2 = mask ? expf(leaky(a.z + b.z)) : 0.f;
    float p3 = mask ? expf(leaky(a.w + b.w)) : 0.f;
    ((float4*)logits)[e] = make_float4(p0, p1, p2, p3);
    asm volatile("red.global.add.v4.f32 [%0], {%1, %2, %3, %4};"
                 :: "l"(denom + d * 4), "f"(p0), "f"(p1), "f"(p2), "f"(p3) : "memory");
}

// pass3: xs is fp16; warp per edge
__global__ void gat_pass3_kernel(const int* __restrict__ src, const int* __restrict__ dst,
                                 const float* __restrict__ logits,
                                 const float* __restrict__ denom,
                                 float* __restrict__ agg, int E, int n_loop) {
    int w = (blockIdx.x * blockDim.x + threadIdx.x) >> 5;
    int lane = threadIdx.x & 31;
    if (w >= E + n_loop) return;
    int s, d;
    if (w < E) { s = src[w]; d = dst[w]; }
    else       { s = d = w - E; }
    float4 P = ((const float4*)logits)[w];
    float4 D = ((const float4*)denom)[d];
    float a0 = 0.25f * P.x / (D.x > 0.f ? D.x : 1.f);
    float a1 = 0.25f * P.y / (D.y > 0.f ? D.y : 1.f);
    float a2 = 0.25f * P.z / (D.z > 0.f ? D.z : 1.f);
    float a3 = 0.25f * P.w / (D.w > 0.f ? D.w : 1.f);
    const __half* xr = g_xs + (size_t)s * 512 + lane * 4;
    float r0 = 0.f, r1 = 0.f, r2 = 0.f, r3 = 0.f;
    float ah[4] = {a0, a1, a2, a3};
#pragma unroll
    for (int h = 0; h < 4; h++) {
        uint2 u = *(const uint2*)(xr + h * 128);
        float2 f01 = __half22float2(*(const __half2*)&u.x);
        float2 f23 = __half22float2(*(const __half2*)&u.y);
        r0 += ah[h] * f01.x; r1 += ah[h] * f01.y;
        r2 += ah[h] * f23.x; r3 += ah[h] * f23.y;
    }
    float* out = agg + (size_t)d * CH + lane * 4;
    asm volatile("red.global.add.v4.f32 [%0], {%1, %2, %3, %4};"
                 :: "l"(out), "f"(r0), "f"(r1), "f"(r2), "f"(r3) : "memory");
}

// combine: gout = [BN(gin) if scale] + agg + bias; optional dual folds (ld2, ls2)
__global__ void combine_kernel(const float* __restrict__ gin, float* __restrict__ gout,
                               const float* __restrict__ bias,
                               const float* __restrict__ agg,
                               const float* __restrict__ scale,
                               const float* __restrict__ shift,
                               const float* __restrict__ wld, float* __restrict__ ld_out,
                               const float* __restrict__ wls, float* __restrict__ ls_out) {
    int i = blockIdx.x * blockDim.x + threadIdx.x;
    if (i >= NGENE * 32) return;
    int c = (i & 31) * 4;
    float4 v = ((const float4*)gin)[i];
    if (scale) {
        v.x = v.x * scale[c + 0] + shift[c + 0];
        v.y = v.y * scale[c + 1] + shift[c + 1];
        v.z = v.z * scale[c + 2] + shift[c + 2];
        v.w = v.w * scale[c + 3] + shift[c + 3];
    }
    float4 ag = ((const float4*)agg)[i];
    v.x += ag.x + bias[c + 0];
    v.y += ag.y + bias[c + 1];
    v.z += ag.z + bias[c + 2];
    v.w += ag.w + bias[c + 3];
    ((float4*)gout)[i] = v;
    if (wld) {
        float4 w0 = ((const float4*)wld)[c + 0];
        float4 w1 = ((const float4*)wld)[c + 1];
        float4 w2 = ((const float4*)wld)[c + 2];
        float4 w3 = ((const float4*)wld)[c + 3];
        float p0 = v.x * w0.x + v.y * w1.x + v.z * w2.x + v.w * w3.x;
        float p1 = v.x * w0.y + v.y * w1.y + v.z * w2.y + v.w * w3.y;
        float p2 = v.x * w0.z + v.y * w1.z + v.z * w2.z + v.w * w3.z;
        float p3 = v.x * w0.w + v.y * w1.w + v.z * w2.w + v.w * w3.w;
        float4 u0 = ((const float4*)wls)[c + 0];
        float4 u1 = ((const float4*)wls)[c + 1];
        float4 u2 = ((const float4*)wls)[c + 2];
        float4 u3 = ((const float4*)wls)[c + 3];
        float q0 = v.x * u0.x + v.y * u1.x + v.z * u2.x + v.w * u3.x;
        float q1 = v.x * u0.y + v.y * u1.y + v.z * u2.y + v.w * u3.y;
        float q2 = v.x * u0.z + v.y * u1.z + v.z * u2.z + v.w * u3.z;
        float q3 = v.x * u0.w + v.y * u1.w + v.z * u2.w + v.w * u3.w;
#pragma unroll
        for (int off = 16; off > 0; off >>= 1) {
            p0 += __shfl_xor_sync(0xffffffffu, p0, off);
            p1 += __shfl_xor_sync(0xffffffffu, p1, off);
            p2 += __shfl_xor_sync(0xffffffffu, p2, off);
            p3 += __shfl_xor_sync(0xffffffffu, p3, off);
            q0 += __shfl_xor_sync(0xffffffffu, q0, off);
            q1 += __shfl_xor_sync(0xffffffffu, q1, off);
            q2 += __shfl_xor_sync(0xffffffffu, q2, off);
            q3 += __shfl_xor_sync(0xffffffffu, q3, off);
        }
        if ((i & 31) == 0) {
            ((float4*)ld_out)[i >> 5] = make_float4(p0, p1, p2, p3);
            ((float4*)ls_out)[i >> 5] = make_float4(q0, q1, q2, q3);
        }
    }
}

// ---------------- launch ----------------
#define SYM(p, s) cudaGetSymbolAddress((void**)&p, s)

extern "C" void kernel_launch(void* const* d_in, const int* in_sizes, int n_in,
                              void* d_out, int out_size) {
    const float* x_gene = (const float*)d_in[0];
    const float* x_dis  = (const float*)d_in[1];
    const int* e1_src = (const int*)d_in[2];
    const int* e1_dst = (const int*)d_in[3];
    const int* e2_src = (const int*)d_in[4];
    const int* e2_dst = (const int*)d_in[5];
    const float* Wg = (const float*)d_in[6];
    const float* bg = (const float*)d_in[7];
    const float* gg = (const float*)d_in[8];
    const float* betag = (const float*)d_in[9];
    const float* Wd = (const float*)d_in[10];
    const float* bd = (const float*)d_in[11];
    const float* gd = (const float*)d_in[12];
    const float* betad = (const float*)d_in[13];
    const float* W1s = (const float*)d_in[14];
    const float* W1d = (const float*)d_in[15];
    const float* a1s = (const float*)d_in[16];
    const float* a1d = (const float*)d_in[17];
    const float* b1  = (const float*)d_in[18];
    const float* W2s = (const float*)d_in[19];
    const float* W2d = (const float*)d_in[20];
    const float* a2s = (const float*)d_in[21];
    const float* a2d = (const float*)d_in[22];
    const float* b2  = (const float*)d_in[23];

    float* out_gene = (float*)d_out;
    float* out_dis  = (float*)d_out + (size_t)NGENE * CH;

    __half *xs, *bt1f, *bt2f;
    float *geneA, *disA, *zb1, *zb2, *ls1, *ls2, *ld1, *ld2, *lg1, *lg2;
    float *wld1, *wld2, *wls1, *wls2, *wldpg, *ldoffg, *wlspd, *lsoffd;
    float *psG, *pqG, *psD, *pqD, *scG, *shG, *scD, *shD;
    __nv_bfloat16 *btg_h, *btg_l, *btd_h, *btd_l;
    SYM(xs, g_xs); SYM(geneA, g_geneA); SYM(disA, g_disA);
    SYM(zb1, g_zb1); SYM(zb2, g_zb2);
    SYM(ls1, g_ls1); SYM(ls2, g_ls2); SYM(ld1, g_ld1); SYM(ld2, g_ld2);
    SYM(lg1, g_logits1); SYM(lg2, g_logits2);
    SYM(wld1, g_wld1); SYM(wld2, g_wld2); SYM(wls1, g_wls1); SYM(wls2, g_wls2);
    SYM(wldpg, g_wldpg); SYM(ldoffg, g_ldoffg); SYM(wlspd, g_wlspd); SYM(lsoffd, g_lsoffd);
    SYM(psG, g_psG); SYM(pqG, g_pqG); SYM(psD, g_psD); SYM(pqD, g_pqD);
    SYM(scG, g_scaleG); SYM(shG, g_shiftG); SYM(scD, g_scaleD); SYM(shD, g_shiftD);
    SYM(btg_h, g_btg_hi); SYM(btg_l, g_btg_lo); SYM(btd_h, g_btd_hi); SYM(btd_l, g_btd_lo);
    SYM(bt1f, g_bt1f16); SYM(bt2f, g_bt2f16);

    float* agg1 = zb1;  float* dn1 = zb1 + (size_t)NGENE * CH;
    float* agg2 = zb2;  float* dn2 = zb2 + (size_t)NGENE * CH;

    cudaStream_t s1, s2;
    cudaStreamCreateWithFlags(&s1, cudaStreamNonBlocking);
    cudaStreamCreateWithFlags(&s2, cudaStreamNonBlocking);
    cudaEvent_t e0, e_prep, e_ls1, e_xs1, e_z1, e_z2, e_c1, e_e2;
    cudaEventCreateWithFlags(&e0, cudaEventDisableTiming);
    cudaEventCreateWithFlags(&e_prep, cudaEventDisableTiming);
    cudaEventCreateWithFlags(&e_ls1, cudaEventDisableTiming);
    cudaEventCreateWithFlags(&e_xs1, cudaEventDisableTiming);
    cudaEventCreateWithFlags(&e_z1, cudaEventDisableTiming);
    cudaEventCreateWithFlags(&e_z2, cudaEventDisableTiming);
    cudaEventCreateWithFlags(&e_c1, cudaEventDisableTiming);
    cudaEventCreateWithFlags(&e_e2, cudaEventDisableTiming);

    cudaEventRecord(e0, 0);
    cudaStreamWaitEvent(s1, e0, 0);
    cudaStreamWaitEvent(s2, e0, 0);

    const int GY_G = (NGENE + 127) / 128;   // 391
    const int GY_D = (NDIS + 127) / 128;    // 196

    // ---- s2: single prep kernel + zeroing ----
    prep_kernel<<<1152, 256, 0, s2>>>(Wg, Wd, W1s, W2s, W1d, a1d, W2d, a2d, a1s, a2s);
    cudaEventRecord(e_prep, s2);
    cudaMemsetAsync(zb1, 0, (size_t)NGENE * (CH + 4) * sizeof(float), s2);
    cudaEventRecord(e_z1, s2);
    cudaMemsetAsync(zb2, 0, (size_t)NGENE * (CH + 4) * sizeof(float), s2);
    cudaEventRecord(e_z2, s2);

    // ---- s1: dis encode -> ls1 -> xs1 GEMM (fp16 single-term, fp16 C) ----
    cudaStreamWaitEvent(s1, e_prep, 0);
    gemm_mma_kernel<1 | 2 | 8><<<dim3(1, GY_D), 256, 0, s1>>>(
        x_dis, btd_h, btd_l, bd, psD, pqD, nullptr, nullptr, nullptr,
        disA, NDIS, CH, FDIS);
    bn_params_kernel<<<1, 512, 0, s1>>>(gd, betad, psD, pqD, GY_D, NDIS, scD, shD,
                                        wls1, wlspd, lsoffd);
    ld_raw_kernel<<<(NDIS * 32 + 255) / 256, 256, 0, s1>>>(disA, NDIS, wlspd, lsoffd, ls1);
    cudaEventRecord(e_ls1, s1);
    gemm_mma_kernel<32 | 64 | 128><<<dim3(4, GY_D), 256, 0, s1>>>(
        disA, bt1f, nullptr, nullptr, nullptr, nullptr, scD, shD, out_dis,
        xs, NDIS, 512, CH);
    cudaEventRecord(e_xs1, s1);

    // ---- s0: gene encode -> ld1 ----
    cudaStreamWaitEvent(0, e_prep, 0);
    gemm_mma_kernel<1 | 2 | 8><<<dim3(1, GY_G), 256>>>(
        x_gene, btg_h, btg_l, bg, psG, pqG, nullptr, nullptr, nullptr,
        geneA, NGENE, CH, FGENE);
    bn_params_kernel<<<1, 512>>>(gg, betag, psG, pqG, GY_G, NGENE, scG, shG,
                                 wld1, wldpg, ldoffg);
    ld_raw_kernel<<<(NGENE * 32 + 255) / 256, 256>>>(geneA, NGENE, wldpg, ldoffg, ld1);

    // ---- relation 1 on s0 ----
    cudaStreamWaitEvent(0, e_ls1, 0);
    cudaStreamWaitEvent(0, e_z1, 0);
    {
        const int E = NE, n_loop = NDIS, ET = E + n_loop;
        gat_edge_kernel<<<(ET + 255) / 256, 256>>>(e1_src, e1_dst, ls1, ld1, dn1, lg1, E, n_loop);
        cudaStreamWaitEvent(0, e_xs1, 0);
        gat_pass3_kernel<<<(ET + 7) / 8, 256>>>(e1_src, e1_dst, lg1, dn1, agg1, E, n_loop);
    }
    // combine1: BN(geneA)+agg1+b1 -> geneA, dual fold -> ld2, ls2
    combine_kernel<<<(NGENE * 32 + 255) / 256, 256>>>(geneA, geneA, b1, agg1,
                                                      scG, shG, wld2, ld2, wls2, ls2);
    cudaEventRecord(e_c1, 0);

    // ---- relation 2: xs2 GEMM (fp16 single-term) on s0, edge2 on s1 ----
    gemm_mma_kernel<64 | 128><<<dim3(4, GY_G), 256>>>(
        geneA, bt2f, nullptr, nullptr, nullptr, nullptr, nullptr, nullptr, nullptr,
        xs, NGENE, 512, CH);
    cudaStreamWaitEvent(s1, e_c1, 0);
    cudaStreamWaitEvent(s1, e_z2, 0);
    {
        const int E = NE, n_loop = NGENE, ET = E + n_loop;
        gat_edge_kernel<<<(ET + 255) / 256, 256, 0, s1>>>(e2_src, e2_dst, ls2, ld2, dn2, lg2,
                                                          E, n_loop);
        cudaEventRecord(e_e2, s1);
        cudaStreamWaitEvent(0, e_e2, 0);
        gat_pass3_kernel<<<(ET + 7) / 8, 256>>>(e2_src, e2_dst, lg2, dn2, agg2, E, n_loop);
    }
    combine_kernel<<<(NGENE * 32 + 255) / 256, 256>>>(geneA, out_gene, b2, agg2,
                                                      nullptr, nullptr, nullptr, nullptr,
                                                      nullptr, nullptr);

    cudaEventDestroy(e0);
    cudaEventDestroy(e_prep);
    cudaEventDestroy(e_ls1);
    cudaEventDestroy(e_xs1);
    cudaEventDestroy(e_z1);
    cudaEventDestroy(e_z2);
    cudaEventDestroy(e_c1);
    cudaEventDestroy(e_e2);
    cudaStreamDestroy(s1);
    cudaStreamDestroy(s2);
}

// round 16
// speedup vs baseline: 1.2569x; 1.1135x over previous
#include <cuda_runtime.h>
#include <cuda_bf16.h>
#include <cuda_fp16.h>
#include <math.h>
#include <cstdint>

#define NGENE 50000
#define NDIS  25000
#define FGENE 512
#define FDIS  256
#define CH    128
#define NE    150000

// ---------------- scratch ----------------
__device__ __half g_xs[(size_t)NGENE * 512];         // fp16 value tensor
__device__ float  g_geneA[(size_t)NGENE * CH];
__device__ float  g_disA[(size_t)NDIS * CH];
__device__ float  g_zb1[(size_t)NGENE * (CH + 4)];   // agg1 | denom1
__device__ float  g_zb2[(size_t)NGENE * (CH + 4)];   // agg2 | denom2
__device__ float  g_ls1[NGENE * 4];
__device__ float  g_ls2[NGENE * 4];
__device__ float  g_ld1[NGENE * 4];
__device__ float  g_ld2[NGENE * 4];
__device__ float  g_logits1[(NE + NDIS) * 4];
__device__ float  g_logits2[(NE + NGENE) * 4];
__device__ float  g_wld1[512], g_wld2[512], g_wls1[512], g_wls2[512];
__device__ float  g_wldpg[512], g_ldoffg[4];
__device__ float  g_wlspd[512], g_lsoffd[4];
__device__ float  g_psG[400 * 128], g_pqG[400 * 128];
__device__ float  g_psD[400 * 128], g_pqD[400 * 128];
__device__ float  g_scaleG[CH], g_shiftG[CH], g_scaleD[CH], g_shiftD[CH];
__device__ __align__(256) __half g_btgf16[512 * 128];   // fp16 Wg^T
__device__ __align__(256) __half g_btdf16[256 * 128];   // fp16 Wd^T
__device__ __align__(256) __half g_bt1f16[512 * 128];   // fp16 W1s^T
__device__ __align__(256) __half g_bt2f16[512 * 128];   // fp16 W2s^T

// ---------------- small helpers ----------------
__device__ __forceinline__ float leaky(float x) { return x > 0.f ? x : 0.2f * x; }
__device__ __forceinline__ uint32_t smem_u32(const void* p) {
    uint32_t a;
    asm("{ .reg .u64 t; cvta.to.shared.u64 t, %1; cvt.u32.u64 %0, t; }" : "=r"(a) : "l"(p));
    return a;
}
__device__ __forceinline__ void mma16816h(float* c, const uint32_t* a,
                                          uint32_t b0, uint32_t b1) {
    asm volatile("mma.sync.aligned.m16n8k16.row.col.f32.f16.f16.f32 "
                 "{%0,%1,%2,%3}, {%4,%5,%6,%7}, {%8,%9}, {%0,%1,%2,%3};"
                 : "+f"(c[0]), "+f"(c[1]), "+f"(c[2]), "+f"(c[3])
                 : "r"(a[0]), "r"(a[1]), "r"(a[2]), "r"(a[3]), "r"(b0), "r"(b1));
}
__device__ __forceinline__ void ldmx4(uint32_t* r, uint32_t addr) {
    asm volatile("ldmatrix.sync.aligned.m8n8.x4.shared.b16 {%0,%1,%2,%3}, [%4];"
                 : "=r"(r[0]), "=r"(r[1]), "=r"(r[2]), "=r"(r[3]) : "r"(addr));
}
__device__ __forceinline__ void cp16(uint32_t saddr, const void* g) {
    asm volatile("cp.async.cg.shared.global [%0], [%1], 16;" :: "r"(saddr), "l"(g));
}
__device__ __forceinline__ void cp_commit() {
    asm volatile("cp.async.commit_group;" ::: "memory");
}
template <int N_>
__device__ __forceinline__ void cp_wait() {
    asm volatile("cp.async.wait_group %0;" :: "n"(N_) : "memory");
}
__device__ __forceinline__ uint32_t pack_hf2(float x, float y) {
    __half2 t = __floats2half2_rn(x, y);
    return *(uint32_t*)&t;
}

// ---------------- batched prep: 4 fp16 weight transposes + 4 folds ----------------
__device__ __forceinline__ void half_body(const float* B, __half* t, int K, int N,
                                          int idx, int total) {
    if (idx >= total) return;
    int k = idx / N, n = idx % N;
    t[(size_t)n * K + k] = __float2half(B[idx]);
}
__device__ __forceinline__ void fold_body(const float* W, const float* a,
                                          float* out, int w, int lane) {
    int k = w >> 2, h = w & 3;
    float4 x = ((const float4*)(W + (size_t)k * 512 + h * 128))[lane];
    float4 y = ((const float4*)(a + h * 128))[lane];
    float s = x.x * y.x + x.y * y.y + x.z * y.z + x.w * y.w;
#pragma unroll
    for (int off = 16; off > 0; off >>= 1)
        s += __shfl_xor_sync(0xffffffffu, s, off);
    if (lane == 0) out[k * 4 + h] = s;
}

__global__ void prep_kernel(const float* __restrict__ Wg, const float* __restrict__ Wd,
                            const float* __restrict__ W1s, const float* __restrict__ W2s,
                            const float* __restrict__ W1d, const float* __restrict__ a1d,
                            const float* __restrict__ W2d, const float* __restrict__ a2d,
                            const float* __restrict__ a1s, const float* __restrict__ a2s) {
    const int b = blockIdx.x, tid = threadIdx.x;
    if (b < 256) {
        half_body(W1s, g_bt1f16, CH, 512, b * 256 + tid, CH * 512);
    } else if (b < 512) {
        half_body(W2s, g_bt2f16, CH, 512, (b - 256) * 256 + tid, CH * 512);
    } else if (b < 768) {
        half_body(Wg, g_btgf16, FGENE, CH, (b - 512) * 256 + tid, FGENE * CH);
    } else if (b < 896) {
        half_body(Wd, g_btdf16, FDIS, CH, (b - 768) * 256 + tid, FDIS * CH);
    } else if (b < 960) {
        fold_body(W1d, a1d, g_wld1, (b - 896) * 8 + (tid >> 5), tid & 31);
    } else if (b < 1024) {
        fold_body(W2d, a2d, g_wld2, (b - 960) * 8 + (tid >> 5), tid & 31);
    } else if (b < 1088) {
        fold_body(W1s, a1s, g_wls1, (b - 1024) * 8 + (tid >> 5), tid & 31);
    } else {
        fold_body(W2s, a2s, g_wls2, (b - 1088) * 8 + (tid >> 5), tid & 31);
    }
}

// ---------------- single-fp16 GEMM (templated on FLAGS) ----------------
// FLAGS: 1=bias, 2=relu, 8=colsum partials, 32=BN A-transform (bx==0 -> Aout),
//        64=store C fp16
#define SST 40

template <int FLAGS>
__global__ __launch_bounds__(256, 2)
void gemm_mma_kernel(const float* __restrict__ A,
                     const __half* __restrict__ Bt,
                     const float* __restrict__ bias,
                     float* __restrict__ ps, float* __restrict__ pq,
                     const float* __restrict__ ascale, const float* __restrict__ ashift,
                     float* __restrict__ Aout,
                     void* __restrict__ Cv, int M, int N, int K)
{
    __shared__ __align__(16) __half smem[2][2][128 * SST];   // A, B
    __shared__ float cs[128], cq[128];

    const int tid = threadIdx.x, wid = tid >> 5, lane = tid & 31;
    const int bm = blockIdx.y * 128, bn = blockIdx.x * 128;
    const int wm = (wid & 3) * 32, wn = (wid >> 2) * 64;
    const int lr = lane >> 2, lc = (lane & 3) * 2;
    const uint32_t sbase = smem_u32(&smem[0][0][0]);
    const uint32_t tilebytes = 128 * SST * 2;

    if ((FLAGS & 8) && tid < 128) { cs[tid] = 0.f; cq[tid] = 0.f; }

    float acc[2][8][4];
#pragma unroll
    for (int mt = 0; mt < 2; mt++)
#pragma unroll
        for (int nt = 0; nt < 8; nt++)
#pragma unroll
            for (int j = 0; j < 4; j++) acc[mt][nt][j] = 0.f;

    const int br_ = tid >> 2, bc8_ = (tid & 3) * 8;
    const int ar = tid >> 1, ac = (tid & 1) * 16;
    const bool arow_ok = (bm + ar < M);
    const int agr = arow_ok ? (bm + ar) : (M - 1);

    float av[16];

    auto ldgA = [&](int k0) {
        const float4* p = (const float4*)(A + (size_t)agr * K + k0 + ac);
        float4 v0 = p[0], v1 = p[1], v2 = p[2], v3 = p[3];
        av[0] = v0.x; av[1] = v0.y; av[2] = v0.z; av[3] = v0.w;
        av[4] = v1.x; av[5] = v1.y; av[6] = v1.z; av[7] = v1.w;
        av[8] = v2.x; av[9] = v2.y; av[10] = v2.z; av[11] = v2.w;
        av[12] = v3.x; av[13] = v3.y; av[14] = v3.z; av[15] = v3.w;
        if (FLAGS & 32) {
            const float4* sc = (const float4*)(ascale + k0 + ac);
            const float4* sh = (const float4*)(ashift + k0 + ac);
#pragma unroll
            for (int q = 0; q < 4; q++) {
                float4 s4 = sc[q], h4 = sh[q];
                av[4 * q + 0] = av[4 * q + 0] * s4.x + h4.x;
                av[4 * q + 1] = av[4 * q + 1] * s4.y + h4.y;
                av[4 * q + 2] = av[4 * q + 2] * s4.z + h4.z;
                av[4 * q + 3] = av[4 * q + 3] * s4.w + h4.w;
            }
            if (blockIdx.x == 0 && arow_ok) {
                float4* o = (float4*)(Aout + (size_t)(bm + ar) * K + k0 + ac);
                o[0] = make_float4(av[0], av[1], av[2], av[3]);
                o[1] = make_float4(av[4], av[5], av[6], av[7]);
                o[2] = make_float4(av[8], av[9], av[10], av[11]);
                o[3] = make_float4(av[12], av[13], av[14], av[15]);
            }
        }
    };
    auto stsA = [&](int buf) {
        const uint32_t off = (uint32_t)(ar * SST + ac) * 2;
        uint32_t hi[8];
#pragma unroll
        for (int j = 0; j < 8; j++) hi[j] = pack_hf2(av[2 * j], av[2 * j + 1]);
        char* base = (char*)&smem[buf][0][0];
        *(uint4*)(base + off)      = make_uint4(hi[0], hi[1], hi[2], hi[3]);
        *(uint4*)(base + off + 16) = make_uint4(hi[4], hi[5], hi[6], hi[7]);
    };
    auto issueB = [&](int buf, int k0) {
#pragma unroll
        for (int h = 0; h < 2; h++) {
            const int r = br_ + h * 64;
            const uint32_t soff = (uint32_t)(r * SST + bc8_) * 2;
            const uint32_t sb = sbase + buf * 2 * tilebytes + tilebytes + soff;
            const size_t boff = (size_t)(bn + r) * K + k0 + bc8_;
            cp16(sb, Bt + boff);
        }
        cp_commit();
    };

    const int nch = K >> 5;
    ldgA(0); issueB(0, 0); stsA(0);

    int buf = 0;
    for (int t = 0; t < nch; t++) {
        const bool has = (t + 1 < nch);
        if (has) {
            ldgA((t + 1) << 5);
            issueB(buf ^ 1, (t + 1) << 5);
            cp_wait<1>();
        } else {
            cp_wait<0>();
        }
        __syncthreads();

        const uint32_t sb = sbase + buf * 2 * tilebytes;
        const uint32_t sA = sb, sB = sb + tilebytes;

        const int arow = wm + (lane & 15);
        const int acol_off = (lane & 16) ? 8 : 0;
        const int brow = wn + (lane & 7) + ((lane & 16) ? 8 : 0);
        const int bcol_off = (lane & 8) ? 8 : 0;

#pragma unroll
        for (int ks = 0; ks < 2; ks++) {
            const int kb = ks * 16;
            uint32_t ah[2][4];
#pragma unroll
            for (int mt = 0; mt < 2; mt++) {
                const uint32_t aaddr = (uint32_t)(((arow + mt * 16) * SST) + kb + acol_off) * 2;
                ldmx4(ah[mt], sA + aaddr);
            }
#pragma unroll
            for (int p = 0; p < 4; p++) {
                uint32_t bh[4];
                const uint32_t baddr = (uint32_t)(((brow + p * 16) * SST) + kb + bcol_off) * 2;
                ldmx4(bh, sB + baddr);
#pragma unroll
                for (int sub = 0; sub < 2; sub++) {
                    const int nt = p * 2 + sub;
                    const uint32_t bh0 = bh[sub * 2], bh1 = bh[sub * 2 + 1];
#pragma unroll
                    for (int mt = 0; mt < 2; mt++)
                        mma16816h(acc[mt][nt], ah[mt], bh0, bh1);
                }
            }
        }
        __syncthreads();
        if (has) stsA(buf ^ 1);
        buf ^= 1;
    }

    // ---------------- epilogue ----------------
    float* Cf = (float*)Cv;
    __half* Ch = (__half*)Cv;
#pragma unroll
    for (int mt = 0; mt < 2; mt++) {
        const int r0 = bm + wm + mt * 16 + lr;
        const bool ok0 = r0 < M, ok1 = (r0 + 8) < M;
#pragma unroll
        for (int nt = 0; nt < 8; nt++) {
            const int col = bn + wn + nt * 8 + lc;
            float2 v0 = make_float2(acc[mt][nt][0], acc[mt][nt][1]);
            float2 v1 = make_float2(acc[mt][nt][2], acc[mt][nt][3]);
            if (FLAGS & 1) {
                float2 bb = *(const float2*)(bias + col);
                v0.x += bb.x; v0.y += bb.y; v1.x += bb.x; v1.y += bb.y;
            }
            if (FLAGS & 2) {
                v0.x = fmaxf(v0.x, 0.f); v0.y = fmaxf(v0.y, 0.f);
                v1.x = fmaxf(v1.x, 0.f); v1.y = fmaxf(v1.y, 0.f);
            }
            if (FLAGS & 64) {
                if (ok0) *(__half2*)(Ch + (size_t)r0 * N + col) = __floats2half2_rn(v0.x, v0.y);
                if (ok1) *(__half2*)(Ch + (size_t)(r0 + 8) * N + col) = __floats2half2_rn(v1.x, v1.y);
            } else {
                if (ok0) *(float2*)(Cf + (size_t)r0 * N + col) = v0;
                if (ok1) *(float2*)(Cf + (size_t)(r0 + 8) * N + col) = v1;
            }
            if (FLAGS & 8) {
                float s0 = (ok0 ? v0.x : 0.f) + (ok1 ? v1.x : 0.f);
                float s1 = (ok0 ? v0.y : 0.f) + (ok1 ? v1.y : 0.f);
                float q0 = (ok0 ? v0.x * v0.x : 0.f) + (ok1 ? v1.x * v1.x : 0.f);
                float q1 = (ok0 ? v0.y * v0.y : 0.f) + (ok1 ? v1.y * v1.y : 0.f);
                const int cc = wn + nt * 8 + lc;
                atomicAdd(&cs[cc], s0); atomicAdd(&cs[cc + 1], s1);
                atomicAdd(&cq[cc], q0); atomicAdd(&cq[cc + 1], q1);
            }
        }
    }
    if (FLAGS & 8) {
        __syncthreads();
        if (tid < 128) {
            ps[blockIdx.y * 128 + tid] = cs[tid];
            pq[blockIdx.y * 128 + tid] = cq[tid];
        }
    }
}

// ---------------- BatchNorm params (+ optional fold) ----------------
__global__ void bn_params_kernel(const float* __restrict__ gamma,
                                 const float* __restrict__ beta,
                                 const float* __restrict__ ps,
                                 const float* __restrict__ pq,
                                 int nb, int M,
                                 float* __restrict__ scale, float* __restrict__ shift,
                                 const float* __restrict__ wld_in,
                                 float* __restrict__ wldp, float* __restrict__ ldoff) {
    __shared__ double ss[4][128], sq[4][128];
    __shared__ float fsc[128], fsh[128], soff[4];
    int c = threadIdx.x & 127, part = threadIdx.x >> 7;
    double s = 0.0, q = 0.0;
    for (int b = part; b < nb; b += 4) { s += ps[b * 128 + c]; q += pq[b * 128 + c]; }
    ss[part][c] = s; sq[part][c] = q;
    if (threadIdx.x < 4) soff[threadIdx.x] = 0.f;
    __syncthreads();
    if (threadIdx.x < 128) {
        double S = ss[0][c] + ss[1][c] + ss[2][c] + ss[3][c];
        double Q = sq[0][c] + sq[1][c] + sq[2][c] + sq[3][c];
        double mu = S / M;
        double var = Q / M - mu * mu;
        float sc = gamma[c] * rsqrtf((float)var + 1e-5f);
        float sh = beta[c] - (float)mu * sc;
        scale[c] = sc; shift[c] = sh;
        fsc[c] = sc; fsh[c] = sh;
    }
    if (wld_in) {
        __syncthreads();
        int h = threadIdx.x >> 7;
        float w = wld_in[c * 4 + h];
        wldp[c * 4 + h] = fsc[c] * w;
        float p = fsh[c] * w;
#pragma unroll
        for (int off = 16; off > 0; off >>= 1)
            p += __shfl_xor_sync(0xffffffffu, p, off);
        if ((threadIdx.x & 31) == 0) atomicAdd(&soff[h], p);
        __syncthreads();
        if (threadIdx.x < 4) ldoff[threadIdx.x] = soff[threadIdx.x];
    }
}

// row dot: out[i][h] = sum_c A[i][c]*wldp[c][h] + ldoff[h]  (warp per row)
__global__ void ld_raw_kernel(const float* __restrict__ A, int M,
                              const float* __restrict__ wldp,
                              const float* __restrict__ ldoff,
                              float* __restrict__ ld_out) {
    int i = blockIdx.x * blockDim.x + threadIdx.x;
    if (i >= M * (CH / 4)) return;
    int c = (i & 31) * 4;
    float4 v = ((const float4*)A)[i];
    float4 w0 = ((const float4*)wldp)[c + 0];
    float4 w1 = ((const float4*)wldp)[c + 1];
    float4 w2 = ((const float4*)wldp)[c + 2];
    float4 w3 = ((const float4*)wldp)[c + 3];
    float p0 = v.x * w0.x + v.y * w1.x + v.z * w2.x + v.w * w3.x;
    float p1 = v.x * w0.y + v.y * w1.y + v.z * w2.y + v.w * w3.y;
    float p2 = v.x * w0.z + v.y * w1.z + v.z * w2.z + v.w * w3.z;
    float p3 = v.x * w0.w + v.y * w1.w + v.z * w2.w + v.w * w3.w;
#pragma unroll
    for (int off = 16; off > 0; off >>= 1) {
        p0 += __shfl_xor_sync(0xffffffffu, p0, off);
        p1 += __shfl_xor_sync(0xffffffffu, p1, off);
        p2 += __shfl_xor_sync(0xffffffffu, p2, off);
        p3 += __shfl_xor_sync(0xffffffffu, p3, off);
    }
    if ((i & 31) == 0)
        ((float4*)ld_out)[i >> 5] = make_float4(p0 + ldoff[0], p1 + ldoff[1],
                                                p2 + ldoff[2], p3 + ldoff[3]);
}

// ---------------- GAT pieces ----------------
__global__ void gat_edge_kernel(const int* __restrict__ src, const int* __restrict__ dst,
                                const float* __restrict__ ls, const float* __restrict__ ld,
                                float* __restrict__ denom, float* __restrict__ logits,
                                int E, int n_loop) {
    int e = blockIdx.x * blockDim.x + threadIdx.x;
    if (e >= E + n_loop) return;
    int s, d; bool mask;
    if (e < E) { s = src[e]; d = dst[e]; mask = (s != d); }
    else       { s = d = e - E; mask = true; }
    float4 a = ((const float4*)ls)[s];
    float4 b = ((const float4*)ld)[d];
    float p0 = mask ? expf(leaky(a.x + b.x)) : 0.f;
    float p1 = mask ? expf(leaky(a.y + b.y)) : 0.f;
    float p2 = mask ? expf(leaky(a.z + b.z)) : 0.f;
    float p3 = mask ? expf(leaky(a.w + b.w)) : 0.f;
    ((float4*)logits)[e] = make_float4(p0, p1, p2, p3);
    asm volatile("red.global.add.v4.f32 [%0], {%1, %2, %3, %4};"
                 :: "l"(denom + d * 4), "f"(p0), "f"(p1), "f"(p2), "f"(p3) : "memory");
}

// pass3: xs is fp16; warp per edge
__global__ void gat_pass3_kernel(const int* __restrict__ src, const int* __restrict__ dst,
                                 const float* __restrict__ logits,
                                 const float* __restrict__ denom,
                                 float* __restrict__ agg, int E, int n_loop) {
    int w = (blockIdx.x * blockDim.x + threadIdx.x) >> 5;
    int lane = threadIdx.x & 31;
    if (w >= E + n_loop) return;
    int s, d;
    if (w < E) { s = src[w]; d = dst[w]; }
    else       { s = d = w - E; }
    float4 P = ((const float4*)logits)[w];
    float4 D = ((const float4*)denom)[d];
    float a0 = 0.25f * P.x / (D.x > 0.f ? D.x : 1.f);
    float a1 = 0.25f * P.y / (D.y > 0.f ? D.y : 1.f);
    float a2 = 0.25f * P.z / (D.z > 0.f ? D.z : 1.f);
    float a3 = 0.25f * P.w / (D.w > 0.f ? D.w : 1.f);
    const __half* xr = g_xs + (size_t)s * 512 + lane * 4;
    float r0 = 0.f, r1 = 0.f, r2 = 0.f, r3 = 0.f;
    float ah[4] = {a0, a1, a2, a3};
#pragma unroll
    for (int h = 0; h < 4; h++) {
        uint2 u = *(const uint2*)(xr + h * 128);
        float2 f01 = __half22float2(*(const __half2*)&u.x);
        float2 f23 = __half22float2(*(const __half2*)&u.y);
        r0 += ah[h] * f01.x; r1 += ah[h] * f01.y;
        r2 += ah[h] * f23.x; r3 += ah[h] * f23.y;
    }
    float* out = agg + (size_t)d * CH + lane * 4;
    asm volatile("red.global.add.v4.f32 [%0], {%1, %2, %3, %4};"
                 :: "l"(out), "f"(r0), "f"(r1), "f"(r2), "f"(r3) : "memory");
}

// combine: gout = [BN(gin) if scale] + agg + bias; optional dual folds (ld2, ls2)
__global__ void combine_kernel(const float* __restrict__ gin, float* __restrict__ gout,
                               const float* __restrict__ bias,
                               const float* __restrict__ agg,
                               const float* __restrict__ scale,
                               const float* __restrict__ shift,
                               const float* __restrict__ wld, float* __restrict__ ld_out,
                               const float* __restrict__ wls, float* __restrict__ ls_out) {
    int i = blockIdx.x * blockDim.x + threadIdx.x;
    if (i >= NGENE * 32) return;
    int c = (i & 31) * 4;
    float4 v = ((const float4*)gin)[i];
    if (scale) {
        v.x = v.x * scale[c + 0] + shift[c + 0];
        v.y = v.y * scale[c + 1] + shift[c + 1];
        v.z = v.z * scale[c + 2] + shift[c + 2];
        v.w = v.w * scale[c + 3] + shift[c + 3];
    }
    float4 ag = ((const float4*)agg)[i];
    v.x += ag.x + bias[c + 0];
    v.y += ag.y + bias[c + 1];
    v.z += ag.z + bias[c + 2];
    v.w += ag.w + bias[c + 3];
    ((float4*)gout)[i] = v;
    if (wld) {
        float4 w0 = ((const float4*)wld)[c + 0];
        float4 w1 = ((const float4*)wld)[c + 1];
        float4 w2 = ((const float4*)wld)[c + 2];
        float4 w3 = ((const float4*)wld)[c + 3];
        float p0 = v.x * w0.x + v.y * w1.x + v.z * w2.x + v.w * w3.x;
        float p1 = v.x * w0.y + v.y * w1.y + v.z * w2.y + v.w * w3.y;
        float p2 = v.x * w0.z + v.y * w1.z + v.z * w2.z + v.w * w3.z;
        float p3 = v.x * w0.w + v.y * w1.w + v.z * w2.w + v.w * w3.w;
        float4 u0 = ((const float4*)wls)[c + 0];
        float4 u1 = ((const float4*)wls)[c + 1];
        float4 u2 = ((const float4*)wls)[c + 2];
        float4 u3 = ((const float4*)wls)[c + 3];
        float q0 = v.x * u0.x + v.y * u1.x + v.z * u2.x + v.w * u3.x;
        float q1 = v.x * u0.y + v.y * u1.y + v.z * u2.y + v.w * u3.y;
        float q2 = v.x * u0.z + v.y * u1.z + v.z * u2.z + v.w * u3.z;
        float q3 = v.x * u0.w + v.y * u1.w + v.z * u2.w + v.w * u3.w;
#pragma unroll
        for (int off = 16; off > 0; off >>= 1) {
            p0 += __shfl_xor_sync(0xffffffffu, p0, off);
            p1 += __shfl_xor_sync(0xffffffffu, p1, off);
            p2 += __shfl_xor_sync(0xffffffffu, p2, off);
            p3 += __shfl_xor_sync(0xffffffffu, p3, off);
            q0 += __shfl_xor_sync(0xffffffffu, q0, off);
            q1 += __shfl_xor_sync(0xffffffffu, q1, off);
            q2 += __shfl_xor_sync(0xffffffffu, q2, off);
            q3 += __shfl_xor_sync(0xffffffffu, q3, off);
        }
        if ((i & 31) == 0) {
            ((float4*)ld_out)[i >> 5] = make_float4(p0, p1, p2, p3);
            ((float4*)ls_out)[i >> 5] = make_float4(q0, q1, q2, q3);
        }
    }
}

// ---------------- launch ----------------
#define SYM(p, s) cudaGetSymbolAddress((void**)&p, s)

extern "C" void kernel_launch(void* const* d_in, const int* in_sizes, int n_in,
                              void* d_out, int out_size) {
    const float* x_gene = (const float*)d_in[0];
    const float* x_dis  = (const float*)d_in[1];
    const int* e1_src = (const int*)d_in[2];
    const int* e1_dst = (const int*)d_in[3];
    const int* e2_src = (const int*)d_in[4];
    const int* e2_dst = (const int*)d_in[5];
    const float* Wg = (const float*)d_in[6];
    const float* bg = (const float*)d_in[7];
    const float* gg = (const float*)d_in[8];
    const float* betag = (const float*)d_in[9];
    const float* Wd = (const float*)d_in[10];
    const float* bd = (const float*)d_in[11];
    const float* gd = (const float*)d_in[12];
    const float* betad = (const float*)d_in[13];
    const float* W1s = (const float*)d_in[14];
    const float* W1d = (const float*)d_in[15];
    const float* a1s = (const float*)d_in[16];
    const float* a1d = (const float*)d_in[17];
    const float* b1  = (const float*)d_in[18];
    const float* W2s = (const float*)d_in[19];
    const float* W2d = (const float*)d_in[20];
    const float* a2s = (const float*)d_in[21];
    const float* a2d = (const float*)d_in[22];
    const float* b2  = (const float*)d_in[23];

    float* out_gene = (float*)d_out;
    float* out_dis  = (float*)d_out + (size_t)NGENE * CH;

    __half *xs, *btgf, *btdf, *bt1f, *bt2f;
    float *geneA, *disA, *zb1, *zb2, *ls1, *ls2, *ld1, *ld2, *lg1, *lg2;
    float *wld1, *wld2, *wls1, *wls2, *wldpg, *ldoffg, *wlspd, *lsoffd;
    float *psG, *pqG, *psD, *pqD, *scG, *shG, *scD, *shD;
    SYM(xs, g_xs); SYM(geneA, g_geneA); SYM(disA, g_disA);
    SYM(zb1, g_zb1); SYM(zb2, g_zb2);
    SYM(ls1, g_ls1); SYM(ls2, g_ls2); SYM(ld1, g_ld1); SYM(ld2, g_ld2);
    SYM(lg1, g_logits1); SYM(lg2, g_logits2);
    SYM(wld1, g_wld1); SYM(wld2, g_wld2); SYM(wls1, g_wls1); SYM(wls2, g_wls2);
    SYM(wldpg, g_wldpg); SYM(ldoffg, g_ldoffg); SYM(wlspd, g_wlspd); SYM(lsoffd, g_lsoffd);
    SYM(psG, g_psG); SYM(pqG, g_pqG); SYM(psD, g_psD); SYM(pqD, g_pqD);
    SYM(scG, g_scaleG); SYM(shG, g_shiftG); SYM(scD, g_scaleD); SYM(shD, g_shiftD);
    SYM(btgf, g_btgf16); SYM(btdf, g_btdf16); SYM(bt1f, g_bt1f16); SYM(bt2f, g_bt2f16);

    float* agg1 = zb1;  float* dn1 = zb1 + (size_t)NGENE * CH;
    float* agg2 = zb2;  float* dn2 = zb2 + (size_t)NGENE * CH;

    cudaStream_t s1, s2;
    cudaStreamCreateWithFlags(&s1, cudaStreamNonBlocking);
    cudaStreamCreateWithFlags(&s2, cudaStreamNonBlocking);
    cudaEvent_t e0, e_prep, e_ls1, e_xs1, e_z1, e_z2, e_c1, e_e2;
    cudaEventCreateWithFlags(&e0, cudaEventDisableTiming);
    cudaEventCreateWithFlags(&e_prep, cudaEventDisableTiming);
    cudaEventCreateWithFlags(&e_ls1, cudaEventDisableTiming);
    cudaEventCreateWithFlags(&e_xs1, cudaEventDisableTiming);
    cudaEventCreateWithFlags(&e_z1, cudaEventDisableTiming);
    cudaEventCreateWithFlags(&e_z2, cudaEventDisableTiming);
    cudaEventCreateWithFlags(&e_c1, cudaEventDisableTiming);
    cudaEventCreateWithFlags(&e_e2, cudaEventDisableTiming);

    cudaEventRecord(e0, 0);
    cudaStreamWaitEvent(s1, e0, 0);
    cudaStreamWaitEvent(s2, e0, 0);

    const int GY_G = (NGENE + 127) / 128;   // 391
    const int GY_D = (NDIS + 127) / 128;    // 196

    // ---- s2: single prep kernel + zeroing ----
    prep_kernel<<<1152, 256, 0, s2>>>(Wg, Wd, W1s, W2s, W1d, a1d, W2d, a2d, a1s, a2s);
    cudaEventRecord(e_prep, s2);
    cudaMemsetAsync(zb1, 0, (size_t)NGENE * (CH + 4) * sizeof(float), s2);
    cudaEventRecord(e_z1, s2);
    cudaMemsetAsync(zb2, 0, (size_t)NGENE * (CH + 4) * sizeof(float), s2);
    cudaEventRecord(e_z2, s2);

    // ---- s1: dis encode (fp16) -> ls1 -> xs1 GEMM (fp16) ----
    cudaStreamWaitEvent(s1, e_prep, 0);
    gemm_mma_kernel<1 | 2 | 8><<<dim3(1, GY_D), 256, 0, s1>>>(
        x_dis, btdf, bd, psD, pqD, nullptr, nullptr, nullptr,
        disA, NDIS, CH, FDIS);
    bn_params_kernel<<<1, 512, 0, s1>>>(gd, betad, psD, pqD, GY_D, NDIS, scD, shD,
                                        wls1, wlspd, lsoffd);
    ld_raw_kernel<<<(NDIS * 32 + 255) / 256, 256, 0, s1>>>(disA, NDIS, wlspd, lsoffd, ls1);
    cudaEventRecord(e_ls1, s1);
    gemm_mma_kernel<32 | 64><<<dim3(4, GY_D), 256, 0, s1>>>(
        disA, bt1f, nullptr, nullptr, nullptr, scD, shD, out_dis,
        xs, NDIS, 512, CH);
    cudaEventRecord(e_xs1, s1);

    // ---- s0: gene encode (fp16) -> ld1 ----
    cudaStreamWaitEvent(0, e_prep, 0);
    gemm_mma_kernel<1 | 2 | 8><<<dim3(1, GY_G), 256>>>(
        x_gene, btgf, bg, psG, pqG, nullptr, nullptr, nullptr,
        geneA, NGENE, CH, FGENE);
    bn_params_kernel<<<1, 512>>>(gg, betag, psG, pqG, GY_G, NGENE, scG, shG,
                                 wld1, wldpg, ldoffg);
    ld_raw_kernel<<<(NGENE * 32 + 255) / 256, 256>>>(geneA, NGENE, wldpg, ldoffg, ld1);

    // ---- relation 1 on s0 ----
    cudaStreamWaitEvent(0, e_ls1, 0);
    cudaStreamWaitEvent(0, e_z1, 0);
    {
        const int E = NE, n_loop = NDIS, ET = E + n_loop;
        gat_edge_kernel<<<(ET + 255) / 256, 256>>>(e1_src, e1_dst, ls1, ld1, dn1, lg1, E, n_loop);
        cudaStreamWaitEvent(0, e_xs1, 0);
        gat_pass3_kernel<<<(ET + 7) / 8, 256>>>(e1_src, e1_dst, lg1, dn1, agg1, E, n_loop);
    }
    // combine1: BN(geneA)+agg1+b1 -> geneA, dual fold -> ld2, ls2
    combine_kernel<<<(NGENE * 32 + 255) / 256, 256>>>(geneA, geneA, b1, agg1,
                                                      scG, shG, wld2, ld2, wls2, ls2);
    cudaEventRecord(e_c1, 0);

    // ---- relation 2: xs2 GEMM (fp16) on s0, edge2 on s1 ----
    gemm_mma_kernel<64><<<dim3(4, GY_G), 256>>>(
        geneA, bt2f, nullptr, nullptr, nullptr, nullptr, nullptr, nullptr,
        xs, NGENE, 512, CH);
    cudaStreamWaitEvent(s1, e_c1, 0);
    cudaStreamWaitEvent(s1, e_z2, 0);
    {
        const int E = NE, n_loop = NGENE, ET = E + n_loop;
        gat_edge_kernel<<<(ET + 255) / 256, 256, 0, s1>>>(e2_src, e2_dst, ls2, ld2, dn2, lg2,
                                                          E, n_loop);
        cudaEventRecord(e_e2, s1);
        cudaStreamWaitEvent(0, e_e2, 0);
        gat_pass3_kernel<<<(ET + 7) / 8, 256>>>(e2_src, e2_dst, lg2, dn2, agg2, E, n_loop);
    }
    combine_kernel<<<(NGENE * 32 + 255) / 256, 256>>>(geneA, out_gene, b2, agg2,
                                                      nullptr, nullptr, nullptr, nullptr,
                                                      nullptr, nullptr);

    cudaEventDestroy(e0);
    cudaEventDestroy(e_prep);
    cudaEventDestroy(e_ls1);
    cudaEventDestroy(e_xs1);
    cudaEventDestroy(e_z1);
    cudaEventDestroy(e_z2);
    cudaEventDestroy(e_c1);
    cudaEventDestroy(e_e2);
    cudaStreamDestroy(s1);
    cudaStreamDestroy(s2);
}